// round 9
// baseline (speedup 1.0000x reference)
#include <cuda_runtime.h>
#include <cuda_bf16.h>
#include <cstdint>
#include <math.h>

#define BATCH  4
#define SEQ    2048
#define DIM    512
#define HEADS  8
#define DHEAD  64
#define INNER  512
#define TRIPLE 1536
#define ROWS   (BATCH * SEQ)

typedef uint32_t u32;
typedef __nv_bfloat16 bf16;

// ----------------------------- device scratch ------------------------------
__device__ bf16 g_xh [ROWS * DIM],   g_xl [ROWS * DIM];
__device__ bf16 g_wqh[TRIPLE * DIM], g_wql[TRIPLE * DIM];
__device__ bf16 g_woh[INNER * DIM],  g_wol[INNER * DIM];
__device__ bf16 g_qh [BATCH*HEADS*SEQ*DHEAD], g_ql[BATCH*HEADS*SEQ*DHEAD]; // [b,h,n,dh]
__device__ bf16 g_kh [BATCH*HEADS*SEQ*DHEAD], g_kl[BATCH*HEADS*SEQ*DHEAD]; // [b,h,n,dh]
__device__ bf16 g_vh [BATCH*HEADS*SEQ*DHEAD], g_vl[BATCH*HEADS*SEQ*DHEAD]; // [b,h,n,dh]
__device__ bf16 g_aoh[ROWS * INNER], g_aol[ROWS * INNER];

// ----------------------------- helpers ---------------------------------
__device__ __forceinline__ u32 smem_u32(const void* p) {
    u32 a;
    asm("{ .reg .u64 t; cvta.to.shared.u64 t, %1; cvt.u32.u64 %0, t; }" : "=r"(a) : "l"(p));
    return a;
}
__device__ __forceinline__ void ldsm4(u32& r0, u32& r1, u32& r2, u32& r3, u32 addr) {
    asm volatile("ldmatrix.sync.aligned.m8n8.x4.shared.b16 {%0,%1,%2,%3}, [%4];"
        : "=r"(r0), "=r"(r1), "=r"(r2), "=r"(r3) : "r"(addr));
}
__device__ __forceinline__ void ldsm4t(u32& r0, u32& r1, u32& r2, u32& r3, u32 addr) {
    asm volatile("ldmatrix.sync.aligned.m8n8.x4.trans.shared.b16 {%0,%1,%2,%3}, [%4];"
        : "=r"(r0), "=r"(r1), "=r"(r2), "=r"(r3) : "r"(addr));
}
__device__ __forceinline__ void mma16816(float* c, u32 a0, u32 a1, u32 a2, u32 a3,
                                          u32 b0, u32 b1) {
    asm volatile("mma.sync.aligned.m16n8k16.row.col.f32.bf16.bf16.f32 "
        "{%0,%1,%2,%3}, {%4,%5,%6,%7}, {%8,%9}, {%0,%1,%2,%3};"
        : "+f"(c[0]), "+f"(c[1]), "+f"(c[2]), "+f"(c[3])
        : "r"(a0), "r"(a1), "r"(a2), "r"(a3), "r"(b0), "r"(b1));
}
__device__ __forceinline__ void cpa16(u32 dst, const void* src) {
    asm volatile("cp.async.cg.shared.global [%0], [%1], 16;" :: "r"(dst), "l"(src));
}
#define CP_COMMIT() asm volatile("cp.async.commit_group;" ::: "memory")
#define CP_WAIT(n)  asm volatile("cp.async.wait_group %0;" :: "n"(n) : "memory")

__device__ __forceinline__ void splitbf(float f, bf16& h, bf16& l) {
    h = __float2bfloat16(f);
    l = __float2bfloat16(f - __bfloat162float(h));
}
__device__ __forceinline__ void split2(float x, float y, u32& hi, u32& lo) {
    __nv_bfloat162 h2 = __floats2bfloat162_rn(x, y);
    float rx = x - __low2float(h2);
    float ry = y - __high2float(h2);
    __nv_bfloat162 l2 = __floats2bfloat162_rn(rx, ry);
    hi = *reinterpret_cast<u32*>(&h2);
    lo = *reinterpret_cast<u32*>(&l2);
}

// ---------------------------------------------------------------- LayerNorm
__global__ __launch_bounds__(128)
void ln_kernel(const float* __restrict__ x,
               const float* __restrict__ gamma,
               const float* __restrict__ beta) {
    const int row = blockIdx.x;
    const int t   = threadIdx.x;
    float4 v = ((const float4*)(x + (size_t)row * DIM))[t];
    float s  = v.x + v.y + v.z + v.w;
    float ss = v.x*v.x + v.y*v.y + v.z*v.z + v.w*v.w;
    #pragma unroll
    for (int o = 16; o > 0; o >>= 1) {
        s  += __shfl_xor_sync(0xffffffffu, s,  o);
        ss += __shfl_xor_sync(0xffffffffu, ss, o);
    }
    __shared__ float sh_s[4], sh_ss[4];
    const int w = t >> 5;
    if ((t & 31) == 0) { sh_s[w] = s; sh_ss[w] = ss; }
    __syncthreads();
    s  = sh_s[0] + sh_s[1] + sh_s[2] + sh_s[3];
    ss = sh_ss[0] + sh_ss[1] + sh_ss[2] + sh_ss[3];
    const float mu  = s * (1.0f / DIM);
    const float var = ss * (1.0f / DIM) - mu * mu;
    const float inv = rsqrtf(var + 1e-5f);
    float4 g  = ((const float4*)gamma)[t];
    float4 be = ((const float4*)beta)[t];
    float o0 = (v.x - mu) * inv * g.x + be.x;
    float o1 = (v.y - mu) * inv * g.y + be.y;
    float o2 = (v.z - mu) * inv * g.z + be.z;
    float o3 = (v.w - mu) * inv * g.w + be.w;
    u32 h01, l01, h23, l23;
    split2(o0, o1, h01, l01);
    split2(o2, o3, h23, l23);
    u32* ph = (u32*)(g_xh + (size_t)row * DIM);
    u32* pl = (u32*)(g_xl + (size_t)row * DIM);
    ph[t * 2] = h01; ph[t * 2 + 1] = h23;
    pl[t * 2] = l01; pl[t * 2 + 1] = l23;
}

// ------------------------------------------- weight transpose + bf16 split
template<int WHICH>
__global__ __launch_bounds__(256)
void wprep_kernel(const float* __restrict__ w) {
    const int N = WHICH ? INNER : TRIPLE;
    bf16* th = WHICH ? g_woh : g_wqh;
    bf16* tl = WHICH ? g_wol : g_wql;
    __shared__ float t[32][33];
    const int bx = blockIdx.x * 32;   // n
    const int by = blockIdx.y * 32;   // k
    const int x = threadIdx.x, y = threadIdx.y;
    #pragma unroll
    for (int i = 0; i < 32; i += 8)
        t[y + i][x] = w[(size_t)(by + y + i) * N + bx + x];
    __syncthreads();
    #pragma unroll
    for (int i = 0; i < 32; i += 8) {
        float f = t[x][y + i];
        bf16 h, l; splitbf(f, h, l);
        th[(size_t)(bx + y + i) * DIM + by + x] = h;
        tl[(size_t)(bx + y + i) * DIM + by + x] = l;
    }
}

// ------------------------------------------- HMMA split-bf16 GEMM (cp.async)
// C[8192, NOUT] = A[8192,512] @ W[512,NOUT]; tile 128m x 64n, BK=16, 4 stages.
// 128 threads / 4 warps; warp w owns 32m x 64n (ratio 2.67).
// Stage layout (12288 B): Ah@0 (4K), Al@4096 (4K), Bh@8192 (2K), Bl@10240 (2K).
// Packed rows: 4 rows (32B each) per 128B line, SW128 XOR per line.
// 4 CTAs/SM: independent barrier domains + deep cp.async pipeline.
template<int NOUT, int MODE>
__global__ __launch_bounds__(128, 4)
void hmma_gemm(float* __restrict__ C) {
    __shared__ __align__(128) char sm[49152];   // 4 stages x 12288
    const u32 sb = smem_u32(sm);
    const int tid = threadIdx.x, w = tid >> 5, lane = tid & 31;
    const int bm = blockIdx.y * 128, bn = blockIdx.x * 64;

    const bf16* Ah = MODE ? g_aoh : g_xh;
    const bf16* Al = MODE ? g_aol : g_xl;
    const bf16* Bh = MODE ? g_woh : g_wqh;
    const bf16* Bl = MODE ? g_wol : g_wql;

    // cp.async chunk mapping: chunk c -> line c>>3, slot c&7
    //   dst(c)  = (c>>3)*128 + (((c&7)*16) ^ (((c>>3)&7)<<4))
    //   row(c)  = (c>>3)*4 + ((c&7)>>1) ;  kel(c) = (c&1)*8
    const int cA0 = tid, cA1 = tid + 128, cB = tid;
    const u32 dA0 = (cA0 >> 3) * 128 + (((cA0 & 7) * 16) ^ (((cA0 >> 3) & 7) << 4));
    const u32 dA1 = (cA1 >> 3) * 128 + (((cA1 & 7) * 16) ^ (((cA1 >> 3) & 7) << 4));
    const u32 dB  = (cB  >> 3) * 128 + (((cB  & 7) * 16) ^ (((cB  >> 3) & 7) << 4));
    const int rA0 = (cA0 >> 3) * 4 + ((cA0 & 7) >> 1), eA0 = (cA0 & 1) * 8;
    const int rA1 = (cA1 >> 3) * 4 + ((cA1 & 7) >> 1), eA1 = (cA1 & 1) * 8;
    const int rB  = (cB  >> 3) * 4 + ((cB  & 7) >> 1), eB  = (cB  & 1) * 8;

    const bf16* aH0 = Ah + (size_t)(bm + rA0) * DIM + eA0;
    const bf16* aH1 = Ah + (size_t)(bm + rA1) * DIM + eA1;
    const bf16* aL0 = Al + (size_t)(bm + rA0) * DIM + eA0;
    const bf16* aL1 = Al + (size_t)(bm + rA1) * DIM + eA1;
    const bf16* bH  = Bh + (size_t)(bn + rB)  * DIM + eB;
    const bf16* bL  = Bl + (size_t)(bn + rB)  * DIM + eB;

    // ldmatrix constants (packed 4-rows/line layout)
    const int ar0 = w * 32 + (lane & 15);
    const int ar1 = ar0 + 16;
    const int al0 = ar0 >> 2, al1 = ar1 >> 2;
    const u32 aoff0 = al0 * 128 + ((((ar0 & 3) * 32) + (lane & 16)) ^ ((al0 & 7) << 4));
    const u32 aoff1 = al1 * 128 + ((((ar1 & 3) * 32) + (lane & 16)) ^ ((al1 & 7) << 4));
    const int brow = (lane & 7) + ((lane & 16) >> 1);
    const int bkb  = (lane & 8) << 1;
    u32 boff[4];
    #pragma unroll
    for (int p = 0; p < 4; ++p) {
        const int r = p * 16 + brow, l = r >> 2;
        boff[p] = l * 128 + ((((r & 3) * 32) + bkb) ^ ((l & 7) << 4));
    }

    float acc[16][4];
    #pragma unroll
    for (int j = 0; j < 16; ++j)
        #pragma unroll
        for (int i = 0; i < 4; ++i) acc[j][i] = 0.f;

    // prologue: stages 0,1,2
    #pragma unroll
    for (int s = 0; s < 3; ++s) {
        const u32 base = sb + s * 12288;
        const size_t ko = (size_t)s * 16;
        cpa16(base +         dA0, aH0 + ko);
        cpa16(base +         dA1, aH1 + ko);
        cpa16(base +  4096 + dA0, aL0 + ko);
        cpa16(base +  4096 + dA1, aL1 + ko);
        cpa16(base +  8192 + dB,  bH  + ko);
        cpa16(base + 10240 + dB,  bL  + ko);
        CP_COMMIT();
    }

    for (int kt = 0; kt < 32; ++kt) {
        CP_WAIT(2);
        __syncthreads();
        if (kt + 3 < 32) {
            const u32 base = sb + ((kt + 3) & 3) * 12288;
            const size_t ko = (size_t)(kt + 3) * 16;
            cpa16(base +         dA0, aH0 + ko);
            cpa16(base +         dA1, aH1 + ko);
            cpa16(base +  4096 + dA0, aL0 + ko);
            cpa16(base +  4096 + dA1, aL1 + ko);
            cpa16(base +  8192 + dB,  bH  + ko);
            cpa16(base + 10240 + dB,  bL  + ko);
            CP_COMMIT();
        }
        const u32 base = sb + (kt & 3) * 12288;
        #pragma unroll
        for (int pass = 0; pass < 3; ++pass) {
            const u32 ab = base + (pass == 2 ? 4096 : 0);
            const u32 bb = base + 8192 + (pass == 1 ? 2048 : 0);
            u32 a0, a1, a2, a3, a4, a5, a6, a7;
            ldsm4(a0, a1, a2, a3, ab + aoff0);
            ldsm4(a4, a5, a6, a7, ab + aoff1);
            #pragma unroll
            for (int p = 0; p < 4; ++p) {
                u32 r0, r1, r2, r3;
                ldsm4(r0, r1, r2, r3, bb + boff[p]);
                mma16816(acc[2 * p],         a0, a1, a2, a3, r0, r1);
                mma16816(acc[2 * p + 1],     a0, a1, a2, a3, r2, r3);
                mma16816(acc[8 + 2 * p],     a4, a5, a6, a7, r0, r1);
                mma16816(acc[8 + 2 * p + 1], a4, a5, a6, a7, r2, r3);
            }
        }
    }

    // ---- epilogue: warp covers rows w*32 + {0..15, 16..31}, cols bn..bn+63
    const int q  = lane >> 2;
    const int qq = (lane & 3) * 2;
    #pragma unroll
    for (int half = 0; half < 2; ++half) {
        const int r0 = bm + w * 32 + half * 16 + q;
        float (*af)[4] = &acc[half * 8];
        if (MODE == 1) {
            #pragma unroll
            for (int ja = 0; ja < 8; ++ja) {
                const int col = bn + ja * 8 + qq;
                *(float2*)(C + (size_t)r0 * NOUT + col)       = make_float2(af[ja][0], af[ja][1]);
                *(float2*)(C + (size_t)(r0 + 8) * NOUT + col) = make_float2(af[ja][2], af[ja][3]);
            }
        } else {
            const int part = bn >> 9;            // 0=q 1=k 2=v (64-block never spans parts)
            bf16* dh = (part == 0) ? g_qh : (part == 1 ? g_kh : g_vh);
            bf16* dl = (part == 0) ? g_ql : (part == 1 ? g_kl : g_vl);
            const int h  = (bn & 511) >> 6;      // one head per 64-col block
            const int bb = r0 >> 11, nn = r0 & 2047;
            const size_t hb = ((size_t)(bb * HEADS + h) * SEQ + nn) * DHEAD;
            #pragma unroll
            for (int ja = 0; ja < 8; ++ja) {
                const int d = ja * 8 + qq;
                u32 hi, lo;
                split2(af[ja][0], af[ja][1], hi, lo);
                *(u32*)(dh + hb + d) = hi;
                *(u32*)(dl + hb + d) = lo;
                split2(af[ja][2], af[ja][3], hi, lo);
                *(u32*)(dh + hb + 8 * DHEAD + d) = hi;
                *(u32*)(dl + hb + 8 * DHEAD + d) = lo;
            }
        }
    }
}

// ------------------------------------------- HMMA attention (cp.async)
// Block: 128 thr (4 warps), 64 queries of one (b,h); 32-key tiles, 2-stage ring.
__global__ __launch_bounds__(128, 4)
void hmma_attn(const float* __restrict__ pose, const float* __restrict__ beta_p) {
    __shared__ __align__(128) char sm[49152];
    const u32 sb = smem_u32(sm);
    const int tid = threadIdx.x, w = tid >> 5, lane = tid & 31;
    const int q0 = blockIdx.x * 64, bh = blockIdx.y, b = bh >> 3, h = bh & 7;

    const bf16* kh = g_kh + (size_t)bh * SEQ * DHEAD;
    const bf16* kl = g_kl + (size_t)bh * SEQ * DHEAD;
    const bf16* vh = g_vh + (size_t)bh * SEQ * DHEAD;
    const bf16* vl = g_vl + (size_t)bh * SEQ * DHEAD;

    {
        const bf16* qh = g_qh + ((size_t)bh * SEQ + q0) * DHEAD;
        const bf16* ql = g_ql + ((size_t)bh * SEQ + q0) * DHEAD;
        #pragma unroll
        for (int i = 0; i < 4; ++i) {
            const int c = tid + i * 128, r = c >> 3, s = c & 7;
            const u32 d = r * 128 + ((s * 16) ^ ((r & 7) << 4));
            const size_t off = (size_t)r * DHEAD + s * 8;
            cpa16(sb + d,        qh + off);
            cpa16(sb + 8192 + d, ql + off);
        }
        #pragma unroll
        for (int i = 0; i < 2; ++i) {
            const int c = tid + i * 128, r = c >> 3, s = c & 7;
            const u32 d = r * 128 + ((s * 16) ^ ((r & 7) << 4));
            const size_t off = (size_t)r * DHEAD + s * 8;
            cpa16(sb + 16384 +         d, kh + off);
            cpa16(sb + 16384 +  4096 + d, kl + off);
            cpa16(sb + 16384 +  8192 + d, vh + off);
            cpa16(sb + 16384 + 12288 + d, vl + off);
        }
        CP_COMMIT();
    }

    const float bet = *beta_p;
    const int q  = lane >> 2;
    const int qq = (lane & 3) * 2;
    const float bq0 = bet * __ldg(&pose[(size_t)b * SEQ + q0 + w * 16 + q]);
    const float bq1 = bet * __ldg(&pose[(size_t)b * SEQ + q0 + w * 16 + q + 8]);
    const float* pb = pose + (size_t)b * SEQ;

    const u32 swz  = (u32)((lane & 7) << 4);
    const u32 aoff = (u32)((w * 16 + (lane & 15)) * 128);
    const u32 acb  = (u32)(lane & 16);
    const int brow = (lane & 7) + ((lane & 16) >> 1);
    const u32 bcb  = (u32)((lane & 8) << 1);
    const int vrow = (lane & 7) + (lane & 8);
    const u32 vcb  = (u32)(lane & 16);

    float o[8][4];
    #pragma unroll
    for (int j = 0; j < 8; ++j)
        #pragma unroll
        for (int i = 0; i < 4; ++i) o[j][i] = 0.f;
    float ls0 = 0.f, ls1 = 0.f;

    for (int t = 0; t < 64; ++t) {
        const int j0 = t * 32;
        CP_WAIT(0);
        __syncthreads();
        if (t + 1 < 64) {
            const u32 base = sb + 16384 + ((t + 1) & 1) * 16384;
            #pragma unroll
            for (int i = 0; i < 2; ++i) {
                const int c = tid + i * 128, r = c >> 3, s = c & 7;
                const u32 d = r * 128 + ((s * 16) ^ ((r & 7) << 4));
                const size_t off = (size_t)(j0 + 32 + r) * DHEAD + s * 8;
                cpa16(base +         d, kh + off);
                cpa16(base +  4096 + d, kl + off);
                cpa16(base +  8192 + d, vh + off);
                cpa16(base + 12288 + d, vl + off);
            }
            CP_COMMIT();
        }
        const u32 kb_ = sb + 16384 + (t & 1) * 16384;
        const u32 vb_ = kb_ + 8192;

        float s[4][4];
        #pragma unroll
        for (int j = 0; j < 4; ++j)
            #pragma unroll
            for (int i = 0; i < 4; ++i) s[j][i] = 0.f;
        #pragma unroll
        for (int pass = 0; pass < 3; ++pass) {
            const u32 ab = sb + (pass == 2 ? 8192 : 0);
            const u32 bb = kb_ + (pass == 1 ? 4096 : 0);
            #pragma unroll
            for (int ks = 0; ks < 4; ++ks) {
                const u32 kc = (u32)(ks * 32);
                u32 a0, a1, a2, a3;
                ldsm4(a0, a1, a2, a3, ab + aoff + ((kc + acb) ^ swz));
                #pragma unroll
                for (int p = 0; p < 2; ++p) {
                    u32 r0, r1, r2, r3;
                    ldsm4(r0, r1, r2, r3, bb + (u32)((p * 16 + brow) * 128) + ((kc + bcb) ^ swz));
                    mma16816(s[2 * p],     a0, a1, a2, a3, r0, r1);
                    mma16816(s[2 * p + 1], a0, a1, a2, a3, r2, r3);
                }
            }
        }

        u32 Ph[2][4], Pl[2][4];
        #pragma unroll
        for (int ja = 0; ja < 4; ++ja) {
            const int col = ja * 8 + qq;
            const float bk0 = bet * __ldg(&pb[j0 + col]);
            const float bk1 = bet * __ldg(&pb[j0 + col + 1]);
            float e0 = __expf(fmaf(s[ja][0], 0.125f, bq0 + bk0));
            float e1 = __expf(fmaf(s[ja][1], 0.125f, bq0 + bk1));
            float e2 = __expf(fmaf(s[ja][2], 0.125f, bq1 + bk0));
            float e3 = __expf(fmaf(s[ja][3], 0.125f, bq1 + bk1));
            ls0 += e0 + e1;
            ls1 += e2 + e3;
            const int ka = ja >> 1, base = (ja & 1) * 2;
            split2(e0, e1, Ph[ka][base],     Pl[ka][base]);
            split2(e2, e3, Ph[ka][base + 1], Pl[ka][base + 1]);
        }

        #pragma unroll
        for (int pass = 0; pass < 3; ++pass) {
            const u32 vb = vb_ + (pass == 1 ? 4096 : 0);
            #pragma unroll
            for (int ks = 0; ks < 2; ++ks) {
                const u32* A = (pass == 2) ? Pl[ks] : Ph[ks];
                const u32 rbase = vb + (u32)((ks * 16 + vrow) * 128);
                #pragma unroll
                for (int p = 0; p < 4; ++p) {
                    u32 r0, r1, r2, r3;
                    ldsm4t(r0, r1, r2, r3, rbase + ((u32)(p * 32 + vcb) ^ swz));
                    mma16816(o[2 * p],     A[0], A[1], A[2], A[3], r0, r1);
                    mma16816(o[2 * p + 1], A[0], A[1], A[2], A[3], r2, r3);
                }
            }
        }
    }

    ls0 += __shfl_xor_sync(0xffffffffu, ls0, 1);
    ls0 += __shfl_xor_sync(0xffffffffu, ls0, 2);
    ls1 += __shfl_xor_sync(0xffffffffu, ls1, 1);
    ls1 += __shfl_xor_sync(0xffffffffu, ls1, 2);
    const float inv0 = 1.0f / ls0, inv1 = 1.0f / ls1;

    const int r0 = q0 + w * 16 + q;
    #pragma unroll
    for (int ja = 0; ja < 8; ++ja) {
        const int col = h * DHEAD + ja * 8 + qq;
        u32 hi, lo;
        split2(o[ja][0] * inv0, o[ja][1] * inv0, hi, lo);
        *(u32*)(g_aoh + ((size_t)(b * SEQ + r0)) * INNER + col) = hi;
        *(u32*)(g_aol + ((size_t)(b * SEQ + r0)) * INNER + col) = lo;
        split2(o[ja][2] * inv1, o[ja][3] * inv1, hi, lo);
        *(u32*)(g_aoh + ((size_t)(b * SEQ + r0 + 8)) * INNER + col) = hi;
        *(u32*)(g_aol + ((size_t)(b * SEQ + r0 + 8)) * INNER + col) = lo;
    }
}

// --------------------------------------------------------------- launcher
extern "C" void kernel_launch(void* const* d_in, const int* in_sizes, int n_in,
                              void* d_out, int out_size) {
    const float* x         = (const float*)d_in[0];
    const float* pose_bias = (const float*)d_in[1];
    const float* ln_gamma  = (const float*)d_in[2];
    const float* ln_beta   = (const float*)d_in[3];
    const float* w_qkv     = (const float*)d_in[4];
    const float* w_out     = (const float*)d_in[5];
    const float* beta      = (const float*)d_in[6];
    float* out = (float*)d_out;

    ln_kernel<<<ROWS, 128>>>(x, ln_gamma, ln_beta);
    wprep_kernel<0><<<dim3(TRIPLE / 32, DIM / 32), dim3(32, 8)>>>(w_qkv);
    wprep_kernel<1><<<dim3(INNER / 32, DIM / 32), dim3(32, 8)>>>(w_out);
    hmma_gemm<TRIPLE, 0><<<dim3(TRIPLE / 64, ROWS / 128), 128>>>(nullptr);
    hmma_attn<<<dim3(SEQ / 64, BATCH * HEADS), 128>>>(pose_bias, beta);
    hmma_gemm<INNER, 1><<<dim3(INNER / 64, ROWS / 128), 128>>>(out);
}

// round 10
// speedup vs baseline: 1.0558x; 1.0558x over previous
#include <cuda_runtime.h>
#include <cuda_bf16.h>
#include <cstdint>
#include <math.h>

#define BATCH  4
#define SEQ    2048
#define DIM    512
#define HEADS  8
#define DHEAD  64
#define INNER  512
#define TRIPLE 1536
#define ROWS   (BATCH * SEQ)

typedef uint32_t u32;
typedef __nv_bfloat16 bf16;

// ----------------------------- device scratch ------------------------------
__device__ bf16 g_xh [ROWS * DIM],   g_xl [ROWS * DIM];
__device__ bf16 g_wqh[TRIPLE * DIM], g_wql[TRIPLE * DIM];
__device__ bf16 g_woh[INNER * DIM],  g_wol[INNER * DIM];
__device__ bf16 g_qh [BATCH*HEADS*SEQ*DHEAD], g_ql[BATCH*HEADS*SEQ*DHEAD]; // [b,h,n,dh]
__device__ bf16 g_kh [BATCH*HEADS*SEQ*DHEAD], g_kl[BATCH*HEADS*SEQ*DHEAD]; // [b,h,n,dh]
__device__ bf16 g_vh [BATCH*HEADS*SEQ*DHEAD], g_vl[BATCH*HEADS*SEQ*DHEAD]; // [b,h,n,dh]
__device__ bf16 g_aoh[ROWS * INNER], g_aol[ROWS * INNER];

// ----------------------------- helpers ---------------------------------
__device__ __forceinline__ u32 smem_u32(const void* p) {
    u32 a;
    asm("{ .reg .u64 t; cvta.to.shared.u64 t, %1; cvt.u32.u64 %0, t; }" : "=r"(a) : "l"(p));
    return a;
}
__device__ __forceinline__ void ldsm4(u32& r0, u32& r1, u32& r2, u32& r3, u32 addr) {
    asm volatile("ldmatrix.sync.aligned.m8n8.x4.shared.b16 {%0,%1,%2,%3}, [%4];"
        : "=r"(r0), "=r"(r1), "=r"(r2), "=r"(r3) : "r"(addr));
}
__device__ __forceinline__ void ldsm4t(u32& r0, u32& r1, u32& r2, u32& r3, u32 addr) {
    asm volatile("ldmatrix.sync.aligned.m8n8.x4.trans.shared.b16 {%0,%1,%2,%3}, [%4];"
        : "=r"(r0), "=r"(r1), "=r"(r2), "=r"(r3) : "r"(addr));
}
__device__ __forceinline__ void mma16816(float* c, u32 a0, u32 a1, u32 a2, u32 a3,
                                          u32 b0, u32 b1) {
    asm volatile("mma.sync.aligned.m16n8k16.row.col.f32.bf16.bf16.f32 "
        "{%0,%1,%2,%3}, {%4,%5,%6,%7}, {%8,%9}, {%0,%1,%2,%3};"
        : "+f"(c[0]), "+f"(c[1]), "+f"(c[2]), "+f"(c[3])
        : "r"(a0), "r"(a1), "r"(a2), "r"(a3), "r"(b0), "r"(b1));
}
__device__ __forceinline__ void cpa16(u32 dst, const void* src) {
    asm volatile("cp.async.cg.shared.global [%0], [%1], 16;" :: "r"(dst), "l"(src));
}
#define CP_COMMIT() asm volatile("cp.async.commit_group;" ::: "memory")
#define CP_WAIT(n)  asm volatile("cp.async.wait_group %0;" :: "n"(n) : "memory")

__device__ __forceinline__ void splitbf(float f, bf16& h, bf16& l) {
    h = __float2bfloat16(f);
    l = __float2bfloat16(f - __bfloat162float(h));
}
__device__ __forceinline__ void split2(float x, float y, u32& hi, u32& lo) {
    __nv_bfloat162 h2 = __floats2bfloat162_rn(x, y);
    float rx = x - __low2float(h2);
    float ry = y - __high2float(h2);
    __nv_bfloat162 l2 = __floats2bfloat162_rn(rx, ry);
    hi = *reinterpret_cast<u32*>(&h2);
    lo = *reinterpret_cast<u32*>(&l2);
}

// ---------------------------------------------------------------- LayerNorm
__global__ __launch_bounds__(128)
void ln_kernel(const float* __restrict__ x,
               const float* __restrict__ gamma,
               const float* __restrict__ beta) {
    const int row = blockIdx.x;
    const int t   = threadIdx.x;
    float4 v = ((const float4*)(x + (size_t)row * DIM))[t];
    float s  = v.x + v.y + v.z + v.w;
    float ss = v.x*v.x + v.y*v.y + v.z*v.z + v.w*v.w;
    #pragma unroll
    for (int o = 16; o > 0; o >>= 1) {
        s  += __shfl_xor_sync(0xffffffffu, s,  o);
        ss += __shfl_xor_sync(0xffffffffu, ss, o);
    }
    __shared__ float sh_s[4], sh_ss[4];
    const int w = t >> 5;
    if ((t & 31) == 0) { sh_s[w] = s; sh_ss[w] = ss; }
    __syncthreads();
    s  = sh_s[0] + sh_s[1] + sh_s[2] + sh_s[3];
    ss = sh_ss[0] + sh_ss[1] + sh_ss[2] + sh_ss[3];
    const float mu  = s * (1.0f / DIM);
    const float var = ss * (1.0f / DIM) - mu * mu;
    const float inv = rsqrtf(var + 1e-5f);
    float4 g  = ((const float4*)gamma)[t];
    float4 be = ((const float4*)beta)[t];
    float o0 = (v.x - mu) * inv * g.x + be.x;
    float o1 = (v.y - mu) * inv * g.y + be.y;
    float o2 = (v.z - mu) * inv * g.z + be.z;
    float o3 = (v.w - mu) * inv * g.w + be.w;
    u32 h01, l01, h23, l23;
    split2(o0, o1, h01, l01);
    split2(o2, o3, h23, l23);
    u32* ph = (u32*)(g_xh + (size_t)row * DIM);
    u32* pl = (u32*)(g_xl + (size_t)row * DIM);
    ph[t * 2] = h01; ph[t * 2 + 1] = h23;
    pl[t * 2] = l01; pl[t * 2 + 1] = l23;
}

// ------------------------------------------- weight transpose + bf16 split
template<int WHICH>
__global__ __launch_bounds__(256)
void wprep_kernel(const float* __restrict__ w) {
    const int N = WHICH ? INNER : TRIPLE;
    bf16* th = WHICH ? g_woh : g_wqh;
    bf16* tl = WHICH ? g_wol : g_wql;
    __shared__ float t[32][33];
    const int bx = blockIdx.x * 32;   // n
    const int by = blockIdx.y * 32;   // k
    const int x = threadIdx.x, y = threadIdx.y;
    #pragma unroll
    for (int i = 0; i < 32; i += 8)
        t[y + i][x] = w[(size_t)(by + y + i) * N + bx + x];
    __syncthreads();
    #pragma unroll
    for (int i = 0; i < 32; i += 8) {
        float f = t[x][y + i];
        bf16 h, l; splitbf(f, h, l);
        th[(size_t)(bx + y + i) * DIM + by + x] = h;
        tl[(size_t)(bx + y + i) * DIM + by + x] = l;
    }
}

// ------------------------------------------- HMMA split-bf16 GEMM (cp.async)
// C[8192, NOUT] = A[8192,512] @ W[512,NOUT]; tile 128m x 64n, BK=32, 2 stages.
// 128 threads / 4 warps; warp w owns 32m x 64n.
// Stage (24576 B): Ah@0 (8K), Al@8192 (8K), Bh@16384 (4K), Bl@20480 (4K).
// Rows are 64B (32 bf16); 2 rows per 128B line, SW128 XOR per line.
// 96 MMAs per barrier (was 48) — halves sync overhead.
template<int NOUT, int MODE>
__global__ __launch_bounds__(128, 4)
void hmma_gemm(float* __restrict__ C) {
    __shared__ __align__(128) char sm[49152];   // 2 stages x 24576
    const u32 sb = smem_u32(sm);
    const int tid = threadIdx.x, w = tid >> 5, lane = tid & 31;
    const int bm = blockIdx.y * 128, bn = blockIdx.x * 64;

    const bf16* Ah = MODE ? g_aoh : g_xh;
    const bf16* Al = MODE ? g_aol : g_xl;
    const bf16* Bh = MODE ? g_woh : g_wqh;
    const bf16* Bl = MODE ? g_wol : g_wql;

    // cp.async mapping: chunk c -> line c>>3, slot c&7; 2 rows per line
    //   dst(c) = (c>>3)*128 + (((c&7)*16) ^ (((c>>3)&7)<<4))
    //   row(c) = (c>>3)*2 + ((c&7)>>2) ; kel(c) = ((c&7)&3)*8
    u32 dA[4]; u32 offA[4];            // element offsets within A matrices
    #pragma unroll
    for (int i = 0; i < 4; ++i) {
        const int c = tid + i * 128, l = c >> 3, s = c & 7;
        dA[i] = l * 128 + ((s * 16) ^ ((l & 7) << 4));
        offA[i] = (u32)((bm + l * 2 + (s >> 2)) * DIM + (s & 3) * 8);
    }
    u32 dB[2]; u32 offB[2];
    #pragma unroll
    for (int i = 0; i < 2; ++i) {
        const int c = tid + i * 128, l = c >> 3, s = c & 7;
        dB[i] = l * 128 + ((s * 16) ^ ((l & 7) << 4));
        offB[i] = (u32)((bn + l * 2 + (s >> 2)) * DIM + (s & 3) * 8);
    }

    // ldmatrix addresses, precomputed per k-step (2-rows/line packing):
    //   addr(r, kb) = (r>>1)*128 + (((r&1)*64 + kb) ^ (((r>>1)&7)<<4))
    const int ar0 = w * 32 + (lane & 15), ar1 = ar0 + 16;
    u32 aaddr0[2], aaddr1[2];
    #pragma unroll
    for (int ks = 0; ks < 2; ++ks) {
        const u32 kb = (u32)(lane & 16) + ks * 32;
        aaddr0[ks] = (ar0 >> 1) * 128 + ((((ar0 & 1) * 64) + kb) ^ (((ar0 >> 1) & 7) << 4));
        aaddr1[ks] = (ar1 >> 1) * 128 + ((((ar1 & 1) * 64) + kb) ^ (((ar1 >> 1) & 7) << 4));
    }
    const int brow = (lane & 7) + ((lane & 16) >> 1);
    u32 baddr[4][2];
    #pragma unroll
    for (int p = 0; p < 4; ++p) {
        const int r = p * 16 + brow;
        #pragma unroll
        for (int ks = 0; ks < 2; ++ks) {
            const u32 kb = (u32)((lane & 8) << 1) + ks * 32;
            baddr[p][ks] = (r >> 1) * 128 + ((((r & 1) * 64) + kb) ^ (((r >> 1) & 7) << 4));
        }
    }

    float acc[16][4];
    #pragma unroll
    for (int j = 0; j < 16; ++j)
        #pragma unroll
        for (int i = 0; i < 4; ++i) acc[j][i] = 0.f;

    // prologue: stage 0 (k0 = 0)
    {
        #pragma unroll
        for (int i = 0; i < 4; ++i) {
            cpa16(sb +         dA[i], Ah + offA[i]);
            cpa16(sb +  8192 + dA[i], Al + offA[i]);
        }
        #pragma unroll
        for (int i = 0; i < 2; ++i) {
            cpa16(sb + 16384 + dB[i], Bh + offB[i]);
            cpa16(sb + 20480 + dB[i], Bl + offB[i]);
        }
        CP_COMMIT();
    }

    for (int kt = 0; kt < 16; ++kt) {
        CP_WAIT(0);
        __syncthreads();
        if (kt + 1 < 16) {
            const u32 base = sb + ((kt + 1) & 1) * 24576;
            const u32 ko = (u32)(kt + 1) * 32;
            #pragma unroll
            for (int i = 0; i < 4; ++i) {
                cpa16(base +         dA[i], Ah + offA[i] + ko);
                cpa16(base +  8192 + dA[i], Al + offA[i] + ko);
            }
            #pragma unroll
            for (int i = 0; i < 2; ++i) {
                cpa16(base + 16384 + dB[i], Bh + offB[i] + ko);
                cpa16(base + 20480 + dB[i], Bl + offB[i] + ko);
            }
            CP_COMMIT();
        }
        const u32 base = sb + (kt & 1) * 24576;
        #pragma unroll
        for (int pass = 0; pass < 3; ++pass) {
            const u32 ab = base + (pass == 2 ? 8192 : 0);
            const u32 bb = base + 16384 + (pass == 1 ? 4096 : 0);
            #pragma unroll
            for (int ks = 0; ks < 2; ++ks) {
                u32 a0, a1, a2, a3, a4, a5, a6, a7;
                ldsm4(a0, a1, a2, a3, ab + aaddr0[ks]);
                ldsm4(a4, a5, a6, a7, ab + aaddr1[ks]);
                #pragma unroll
                for (int p = 0; p < 4; ++p) {
                    u32 r0, r1, r2, r3;
                    ldsm4(r0, r1, r2, r3, bb + baddr[p][ks]);
                    mma16816(acc[2 * p],         a0, a1, a2, a3, r0, r1);
                    mma16816(acc[2 * p + 1],     a0, a1, a2, a3, r2, r3);
                    mma16816(acc[8 + 2 * p],     a4, a5, a6, a7, r0, r1);
                    mma16816(acc[8 + 2 * p + 1], a4, a5, a6, a7, r2, r3);
                }
            }
        }
    }

    // ---- epilogue: warp covers rows w*32 + {0..15, 16..31}, cols bn..bn+63
    const int q  = lane >> 2;
    const int qq = (lane & 3) * 2;
    #pragma unroll
    for (int half = 0; half < 2; ++half) {
        const int r0 = bm + w * 32 + half * 16 + q;
        float (*af)[4] = &acc[half * 8];
        if (MODE == 1) {
            #pragma unroll
            for (int ja = 0; ja < 8; ++ja) {
                const int col = bn + ja * 8 + qq;
                *(float2*)(C + (size_t)r0 * NOUT + col)       = make_float2(af[ja][0], af[ja][1]);
                *(float2*)(C + (size_t)(r0 + 8) * NOUT + col) = make_float2(af[ja][2], af[ja][3]);
            }
        } else {
            const int part = bn >> 9;            // 0=q 1=k 2=v (64-block never spans parts)
            bf16* dh = (part == 0) ? g_qh : (part == 1 ? g_kh : g_vh);
            bf16* dl = (part == 0) ? g_ql : (part == 1 ? g_kl : g_vl);
            const int h  = (bn & 511) >> 6;      // one head per 64-col block
            const int bb = r0 >> 11, nn = r0 & 2047;
            const size_t hb = ((size_t)(bb * HEADS + h) * SEQ + nn) * DHEAD;
            #pragma unroll
            for (int ja = 0; ja < 8; ++ja) {
                const int d = ja * 8 + qq;
                u32 hi, lo;
                split2(af[ja][0], af[ja][1], hi, lo);
                *(u32*)(dh + hb + d) = hi;
                *(u32*)(dl + hb + d) = lo;
                split2(af[ja][2], af[ja][3], hi, lo);
                *(u32*)(dh + hb + 8 * DHEAD + d) = hi;
                *(u32*)(dl + hb + 8 * DHEAD + d) = lo;
            }
        }
    }
}

// ------------------------------------------- HMMA attention (cp.async)
// Block: 128 thr (4 warps), 64 queries of one (b,h); 32-key tiles, 2-stage ring.
// (launch bounds reverted to the R8 configuration that measured fastest)
__global__ __launch_bounds__(128, 3)
void hmma_attn(const float* __restrict__ pose, const float* __restrict__ beta_p) {
    __shared__ __align__(128) char sm[49152];
    const u32 sb = smem_u32(sm);
    const int tid = threadIdx.x, w = tid >> 5, lane = tid & 31;
    const int q0 = blockIdx.x * 64, bh = blockIdx.y, b = bh >> 3, h = bh & 7;

    const bf16* kh = g_kh + (size_t)bh * SEQ * DHEAD;
    const bf16* kl = g_kl + (size_t)bh * SEQ * DHEAD;
    const bf16* vh = g_vh + (size_t)bh * SEQ * DHEAD;
    const bf16* vl = g_vl + (size_t)bh * SEQ * DHEAD;

    {
        const bf16* qh = g_qh + ((size_t)bh * SEQ + q0) * DHEAD;
        const bf16* ql = g_ql + ((size_t)bh * SEQ + q0) * DHEAD;
        #pragma unroll
        for (int i = 0; i < 4; ++i) {
            const int c = tid + i * 128, r = c >> 3, s = c & 7;
            const u32 d = r * 128 + ((s * 16) ^ ((r & 7) << 4));
            const size_t off = (size_t)r * DHEAD + s * 8;
            cpa16(sb + d,        qh + off);
            cpa16(sb + 8192 + d, ql + off);
        }
        #pragma unroll
        for (int i = 0; i < 2; ++i) {
            const int c = tid + i * 128, r = c >> 3, s = c & 7;
            const u32 d = r * 128 + ((s * 16) ^ ((r & 7) << 4));
            const size_t off = (size_t)r * DHEAD + s * 8;
            cpa16(sb + 16384 +         d, kh + off);
            cpa16(sb + 16384 +  4096 + d, kl + off);
            cpa16(sb + 16384 +  8192 + d, vh + off);
            cpa16(sb + 16384 + 12288 + d, vl + off);
        }
        CP_COMMIT();
    }

    const float bet = *beta_p;
    const int q  = lane >> 2;
    const int qq = (lane & 3) * 2;
    const float bq0 = bet * __ldg(&pose[(size_t)b * SEQ + q0 + w * 16 + q]);
    const float bq1 = bet * __ldg(&pose[(size_t)b * SEQ + q0 + w * 16 + q + 8]);
    const float* pb = pose + (size_t)b * SEQ;

    const u32 swz  = (u32)((lane & 7) << 4);
    const u32 aoff = (u32)((w * 16 + (lane & 15)) * 128);
    const u32 acb  = (u32)(lane & 16);
    const int brow = (lane & 7) + ((lane & 16) >> 1);
    const u32 bcb  = (u32)((lane & 8) << 1);
    const int vrow = (lane & 7) + (lane & 8);
    const u32 vcb  = (u32)(lane & 16);

    float o[8][4];
    #pragma unroll
    for (int j = 0; j < 8; ++j)
        #pragma unroll
        for (int i = 0; i < 4; ++i) o[j][i] = 0.f;
    float ls0 = 0.f, ls1 = 0.f;

    for (int t = 0; t < 64; ++t) {
        const int j0 = t * 32;
        CP_WAIT(0);
        __syncthreads();
        if (t + 1 < 64) {
            const u32 base = sb + 16384 + ((t + 1) & 1) * 16384;
            #pragma unroll
            for (int i = 0; i < 2; ++i) {
                const int c = tid + i * 128, r = c >> 3, s = c & 7;
                const u32 d = r * 128 + ((s * 16) ^ ((r & 7) << 4));
                const size_t off = (size_t)(j0 + 32 + r) * DHEAD + s * 8;
                cpa16(base +         d, kh + off);
                cpa16(base +  4096 + d, kl + off);
                cpa16(base +  8192 + d, vh + off);
                cpa16(base + 12288 + d, vl + off);
            }
            CP_COMMIT();
        }
        const u32 kb_ = sb + 16384 + (t & 1) * 16384;
        const u32 vb_ = kb_ + 8192;

        float s[4][4];
        #pragma unroll
        for (int j = 0; j < 4; ++j)
            #pragma unroll
            for (int i = 0; i < 4; ++i) s[j][i] = 0.f;
        #pragma unroll
        for (int pass = 0; pass < 3; ++pass) {
            const u32 ab = sb + (pass == 2 ? 8192 : 0);
            const u32 bb = kb_ + (pass == 1 ? 4096 : 0);
            #pragma unroll
            for (int ks = 0; ks < 4; ++ks) {
                const u32 kc = (u32)(ks * 32);
                u32 a0, a1, a2, a3;
                ldsm4(a0, a1, a2, a3, ab + aoff + ((kc + acb) ^ swz));
                #pragma unroll
                for (int p = 0; p < 2; ++p) {
                    u32 r0, r1, r2, r3;
                    ldsm4(r0, r1, r2, r3, bb + (u32)((p * 16 + brow) * 128) + ((kc + bcb) ^ swz));
                    mma16816(s[2 * p],     a0, a1, a2, a3, r0, r1);
                    mma16816(s[2 * p + 1], a0, a1, a2, a3, r2, r3);
                }
            }
        }

        u32 Ph[2][4], Pl[2][4];
        #pragma unroll
        for (int ja = 0; ja < 4; ++ja) {
            const int col = ja * 8 + qq;
            const float bk0 = bet * __ldg(&pb[j0 + col]);
            const float bk1 = bet * __ldg(&pb[j0 + col + 1]);
            float e0 = __expf(fmaf(s[ja][0], 0.125f, bq0 + bk0));
            float e1 = __expf(fmaf(s[ja][1], 0.125f, bq0 + bk1));
            float e2 = __expf(fmaf(s[ja][2], 0.125f, bq1 + bk0));
            float e3 = __expf(fmaf(s[ja][3], 0.125f, bq1 + bk1));
            ls0 += e0 + e1;
            ls1 += e2 + e3;
            const int ka = ja >> 1, base = (ja & 1) * 2;
            split2(e0, e1, Ph[ka][base],     Pl[ka][base]);
            split2(e2, e3, Ph[ka][base + 1], Pl[ka][base + 1]);
        }

        #pragma unroll
        for (int pass = 0; pass < 3; ++pass) {
            const u32 vb = vb_ + (pass == 1 ? 4096 : 0);
            #pragma unroll
            for (int ks = 0; ks < 2; ++ks) {
                const u32* A = (pass == 2) ? Pl[ks] : Ph[ks];
                const u32 rbase = vb + (u32)((ks * 16 + vrow) * 128);
                #pragma unroll
                for (int p = 0; p < 4; ++p) {
                    u32 r0, r1, r2, r3;
                    ldsm4t(r0, r1, r2, r3, rbase + ((u32)(p * 32 + vcb) ^ swz));
                    mma16816(o[2 * p],     A[0], A[1], A[2], A[3], r0, r1);
                    mma16816(o[2 * p + 1], A[0], A[1], A[2], A[3], r2, r3);
                }
            }
        }
    }

    ls0 += __shfl_xor_sync(0xffffffffu, ls0, 1);
    ls0 += __shfl_xor_sync(0xffffffffu, ls0, 2);
    ls1 += __shfl_xor_sync(0xffffffffu, ls1, 1);
    ls1 += __shfl_xor_sync(0xffffffffu, ls1, 2);
    const float inv0 = 1.0f / ls0, inv1 = 1.0f / ls1;

    const int r0 = q0 + w * 16 + q;
    #pragma unroll
    for (int ja = 0; ja < 8; ++ja) {
        const int col = h * DHEAD + ja * 8 + qq;
        u32 hi, lo;
        split2(o[ja][0] * inv0, o[ja][1] * inv0, hi, lo);
        *(u32*)(g_aoh + ((size_t)(b * SEQ + r0)) * INNER + col) = hi;
        *(u32*)(g_aol + ((size_t)(b * SEQ + r0)) * INNER + col) = lo;
        split2(o[ja][2] * inv1, o[ja][3] * inv1, hi, lo);
        *(u32*)(g_aoh + ((size_t)(b * SEQ + r0 + 8)) * INNER + col) = hi;
        *(u32*)(g_aol + ((size_t)(b * SEQ + r0 + 8)) * INNER + col) = lo;
    }
}

// --------------------------------------------------------------- launcher
extern "C" void kernel_launch(void* const* d_in, const int* in_sizes, int n_in,
                              void* d_out, int out_size) {
    const float* x         = (const float*)d_in[0];
    const float* pose_bias = (const float*)d_in[1];
    const float* ln_gamma  = (const float*)d_in[2];
    const float* ln_beta   = (const float*)d_in[3];
    const float* w_qkv     = (const float*)d_in[4];
    const float* w_out     = (const float*)d_in[5];
    const float* beta      = (const float*)d_in[6];
    float* out = (float*)d_out;

    ln_kernel<<<ROWS, 128>>>(x, ln_gamma, ln_beta);
    wprep_kernel<0><<<dim3(TRIPLE / 32, DIM / 32), dim3(32, 8)>>>(w_qkv);
    wprep_kernel<1><<<dim3(INNER / 32, DIM / 32), dim3(32, 8)>>>(w_out);
    hmma_gemm<TRIPLE, 0><<<dim3(TRIPLE / 64, ROWS / 128), 128>>>(nullptr);
    hmma_attn<<<dim3(SEQ / 64, BATCH * HEADS), 128>>>(pose_bias, beta);
    hmma_gemm<INNER, 1><<<dim3(INNER / 64, ROWS / 128), 128>>>(out);
}

// round 11
// speedup vs baseline: 1.4670x; 1.3895x over previous
#include <cuda_runtime.h>
#include <cuda_fp16.h>
#include <cstdint>
#include <math.h>

#define BATCH  4
#define SEQ    2048
#define DIM    512
#define HEADS  8
#define DHEAD  64
#define INNER  512
#define TRIPLE 1536
#define ROWS   (BATCH * SEQ)

typedef uint32_t u32;

// ----------------------------- device scratch ------------------------------
// A-operands split hi/lo (exact); B-operands single-rounded fp16.
__device__ half g_xh [ROWS * DIM],  g_xl [ROWS * DIM];     // LN out split
__device__ half g_wq [TRIPLE * DIM];                        // w_qkv^T fp16 [N][K]
__device__ half g_wo [INNER * DIM];                         // w_out^T fp16
__device__ half g_qh [BATCH*HEADS*SEQ*DHEAD], g_ql[BATCH*HEADS*SEQ*DHEAD]; // [b,h,n,dh]
__device__ half g_k  [BATCH*HEADS*SEQ*DHEAD];               // [b,h,n,dh]
__device__ half g_v  [BATCH*HEADS*SEQ*DHEAD];               // [b,h,n,dh]
__device__ half g_aoh[ROWS * INNER], g_aol[ROWS * INNER];   // attn out split

// ----------------------------- helpers ---------------------------------
__device__ __forceinline__ u32 smem_u32(const void* p) {
    u32 a;
    asm("{ .reg .u64 t; cvta.to.shared.u64 t, %1; cvt.u32.u64 %0, t; }" : "=r"(a) : "l"(p));
    return a;
}
__device__ __forceinline__ void ldsm4(u32& r0, u32& r1, u32& r2, u32& r3, u32 addr) {
    asm volatile("ldmatrix.sync.aligned.m8n8.x4.shared.b16 {%0,%1,%2,%3}, [%4];"
        : "=r"(r0), "=r"(r1), "=r"(r2), "=r"(r3) : "r"(addr));
}
__device__ __forceinline__ void ldsm4t(u32& r0, u32& r1, u32& r2, u32& r3, u32 addr) {
    asm volatile("ldmatrix.sync.aligned.m8n8.x4.trans.shared.b16 {%0,%1,%2,%3}, [%4];"
        : "=r"(r0), "=r"(r1), "=r"(r2), "=r"(r3) : "r"(addr));
}
__device__ __forceinline__ void mma16816(float* c, u32 a0, u32 a1, u32 a2, u32 a3,
                                          u32 b0, u32 b1) {
    asm volatile("mma.sync.aligned.m16n8k16.row.col.f32.f16.f16.f32 "
        "{%0,%1,%2,%3}, {%4,%5,%6,%7}, {%8,%9}, {%0,%1,%2,%3};"
        : "+f"(c[0]), "+f"(c[1]), "+f"(c[2]), "+f"(c[3])
        : "r"(a0), "r"(a1), "r"(a2), "r"(a3), "r"(b0), "r"(b1));
}
__device__ __forceinline__ void cpa16(u32 dst, const void* src) {
    asm volatile("cp.async.cg.shared.global [%0], [%1], 16;" :: "r"(dst), "l"(src));
}
#define CP_COMMIT() asm volatile("cp.async.commit_group;" ::: "memory")
#define CP_WAIT(n)  asm volatile("cp.async.wait_group %0;" :: "n"(n) : "memory")

// split x,y into packed fp16 hi pair + lo (residual) pair
__device__ __forceinline__ void split2h(float x, float y, u32& hi, u32& lo) {
    __half2 h2 = __floats2half2_rn(x, y);
    float rx = x - __low2float(h2);
    float ry = y - __high2float(h2);
    __half2 l2 = __floats2half2_rn(rx, ry);
    hi = *reinterpret_cast<u32*>(&h2);
    lo = *reinterpret_cast<u32*>(&l2);
}
__device__ __forceinline__ u32 pack2h(float x, float y) {
    __half2 h2 = __floats2half2_rn(x, y);
    return *reinterpret_cast<u32*>(&h2);
}

// ---------------------------------------------------------------- LayerNorm
__global__ __launch_bounds__(128)
void ln_kernel(const float* __restrict__ x,
               const float* __restrict__ gamma,
               const float* __restrict__ beta) {
    const int row = blockIdx.x;
    const int t   = threadIdx.x;
    float4 v = ((const float4*)(x + (size_t)row * DIM))[t];
    float s  = v.x + v.y + v.z + v.w;
    float ss = v.x*v.x + v.y*v.y + v.z*v.z + v.w*v.w;
    #pragma unroll
    for (int o = 16; o > 0; o >>= 1) {
        s  += __shfl_xor_sync(0xffffffffu, s,  o);
        ss += __shfl_xor_sync(0xffffffffu, ss, o);
    }
    __shared__ float sh_s[4], sh_ss[4];
    const int w = t >> 5;
    if ((t & 31) == 0) { sh_s[w] = s; sh_ss[w] = ss; }
    __syncthreads();
    s  = sh_s[0] + sh_s[1] + sh_s[2] + sh_s[3];
    ss = sh_ss[0] + sh_ss[1] + sh_ss[2] + sh_ss[3];
    const float mu  = s * (1.0f / DIM);
    const float var = ss * (1.0f / DIM) - mu * mu;
    const float inv = rsqrtf(var + 1e-5f);
    float4 g  = ((const float4*)gamma)[t];
    float4 be = ((const float4*)beta)[t];
    float o0 = (v.x - mu) * inv * g.x + be.x;
    float o1 = (v.y - mu) * inv * g.y + be.y;
    float o2 = (v.z - mu) * inv * g.z + be.z;
    float o3 = (v.w - mu) * inv * g.w + be.w;
    u32 h01, l01, h23, l23;
    split2h(o0, o1, h01, l01);
    split2h(o2, o3, h23, l23);
    u32* ph = (u32*)(g_xh + (size_t)row * DIM);
    u32* pl = (u32*)(g_xl + (size_t)row * DIM);
    ph[t * 2] = h01; ph[t * 2 + 1] = h23;
    pl[t * 2] = l01; pl[t * 2 + 1] = l23;
}

// ------------------------------------------- weight transpose -> fp16
template<int WHICH>
__global__ __launch_bounds__(256)
void wprep_kernel(const float* __restrict__ w) {
    const int N = WHICH ? INNER : TRIPLE;
    half* th = WHICH ? g_wo : g_wq;
    __shared__ float t[32][33];
    const int bx = blockIdx.x * 32;   // n
    const int by = blockIdx.y * 32;   // k
    const int x = threadIdx.x, y = threadIdx.y;
    #pragma unroll
    for (int i = 0; i < 32; i += 8)
        t[y + i][x] = w[(size_t)(by + y + i) * N + bx + x];
    __syncthreads();
    #pragma unroll
    for (int i = 0; i < 32; i += 8)
        th[(size_t)(bx + y + i) * DIM + by + x] = __float2half(t[x][y + i]);
}

// ------------------------------------------- HMMA fp16 2-pass GEMM (cp.async)
// C[8192, NOUT] = (Ah+Al)[8192,512] @ B16[512,NOUT]; tile 128m x 64n, BK=32,
// 2 stages. Stage (20480 B): Ah@0 (8K), Al@8192 (8K), B@16384 (4K).
// Rows 64B; 2 rows per 128B line, SW128 XOR per line. 2 MMA passes (Ah, Al).
template<int NOUT, int MODE>
__global__ __launch_bounds__(128, 4)
void hmma_gemm(float* __restrict__ C) {
    __shared__ __align__(128) char sm[40960];   // 2 stages x 20480
    const u32 sb = smem_u32(sm);
    const int tid = threadIdx.x, w = tid >> 5, lane = tid & 31;
    const int bm = blockIdx.y * 128, bn = blockIdx.x * 64;

    const half* Ah = MODE ? g_aoh : g_xh;
    const half* Al = MODE ? g_aol : g_xl;
    const half* B  = MODE ? g_wo  : g_wq;

    // cp.async mapping: chunk c -> line c>>3, slot c&7; 2 rows per line
    u32 dA[4]; u32 offA[4];
    #pragma unroll
    for (int i = 0; i < 4; ++i) {
        const int c = tid + i * 128, l = c >> 3, s = c & 7;
        dA[i] = l * 128 + ((s * 16) ^ ((l & 7) << 4));
        offA[i] = (u32)((bm + l * 2 + (s >> 2)) * DIM + (s & 3) * 8);
    }
    u32 dB[2]; u32 offB[2];
    #pragma unroll
    for (int i = 0; i < 2; ++i) {
        const int c = tid + i * 128, l = c >> 3, s = c & 7;
        dB[i] = l * 128 + ((s * 16) ^ ((l & 7) << 4));
        offB[i] = (u32)((bn + l * 2 + (s >> 2)) * DIM + (s & 3) * 8);
    }

    // ldmatrix addresses (2-rows/line packing)
    const int ar0 = w * 32 + (lane & 15), ar1 = ar0 + 16;
    u32 aaddr0[2], aaddr1[2];
    #pragma unroll
    for (int ks = 0; ks < 2; ++ks) {
        const u32 kb = (u32)(lane & 16) + ks * 32;
        aaddr0[ks] = (ar0 >> 1) * 128 + ((((ar0 & 1) * 64) + kb) ^ (((ar0 >> 1) & 7) << 4));
        aaddr1[ks] = (ar1 >> 1) * 128 + ((((ar1 & 1) * 64) + kb) ^ (((ar1 >> 1) & 7) << 4));
    }
    const int brow = (lane & 7) + ((lane & 16) >> 1);
    u32 baddr[4][2];
    #pragma unroll
    for (int p = 0; p < 4; ++p) {
        const int r = p * 16 + brow;
        #pragma unroll
        for (int ks = 0; ks < 2; ++ks) {
            const u32 kb = (u32)((lane & 8) << 1) + ks * 32;
            baddr[p][ks] = (r >> 1) * 128 + ((((r & 1) * 64) + kb) ^ (((r >> 1) & 7) << 4));
        }
    }

    float acc[16][4];
    #pragma unroll
    for (int j = 0; j < 16; ++j)
        #pragma unroll
        for (int i = 0; i < 4; ++i) acc[j][i] = 0.f;

    // prologue: stage 0
    {
        #pragma unroll
        for (int i = 0; i < 4; ++i) {
            cpa16(sb +        dA[i], Ah + offA[i]);
            cpa16(sb + 8192 + dA[i], Al + offA[i]);
        }
        #pragma unroll
        for (int i = 0; i < 2; ++i)
            cpa16(sb + 16384 + dB[i], B + offB[i]);
        CP_COMMIT();
    }

    for (int kt = 0; kt < 16; ++kt) {
        CP_WAIT(0);
        __syncthreads();
        if (kt + 1 < 16) {
            const u32 base = sb + ((kt + 1) & 1) * 20480;
            const u32 ko = (u32)(kt + 1) * 32;
            #pragma unroll
            for (int i = 0; i < 4; ++i) {
                cpa16(base +        dA[i], Ah + offA[i] + ko);
                cpa16(base + 8192 + dA[i], Al + offA[i] + ko);
            }
            #pragma unroll
            for (int i = 0; i < 2; ++i)
                cpa16(base + 16384 + dB[i], B + offB[i] + ko);
            CP_COMMIT();
        }
        const u32 base = sb + (kt & 1) * 20480;
        #pragma unroll
        for (int pass = 0; pass < 2; ++pass) {
            const u32 ab = base + pass * 8192;
            const u32 bb = base + 16384;
            #pragma unroll
            for (int ks = 0; ks < 2; ++ks) {
                u32 a0, a1, a2, a3, a4, a5, a6, a7;
                ldsm4(a0, a1, a2, a3, ab + aaddr0[ks]);
                ldsm4(a4, a5, a6, a7, ab + aaddr1[ks]);
                #pragma unroll
                for (int p = 0; p < 4; ++p) {
                    u32 r0, r1, r2, r3;
                    ldsm4(r0, r1, r2, r3, bb + baddr[p][ks]);
                    mma16816(acc[2 * p],         a0, a1, a2, a3, r0, r1);
                    mma16816(acc[2 * p + 1],     a0, a1, a2, a3, r2, r3);
                    mma16816(acc[8 + 2 * p],     a4, a5, a6, a7, r0, r1);
                    mma16816(acc[8 + 2 * p + 1], a4, a5, a6, a7, r2, r3);
                }
            }
        }
    }

    // ---- epilogue: warp covers rows w*32 + {0..15, 16..31}, cols bn..bn+63
    const int q  = lane >> 2;
    const int qq = (lane & 3) * 2;
    #pragma unroll
    for (int half_ = 0; half_ < 2; ++half_) {
        const int r0 = bm + w * 32 + half_ * 16 + q;
        float (*af)[4] = &acc[half_ * 8];
        if (MODE == 1) {
            #pragma unroll
            for (int ja = 0; ja < 8; ++ja) {
                const int col = bn + ja * 8 + qq;
                *(float2*)(C + (size_t)r0 * NOUT + col)       = make_float2(af[ja][0], af[ja][1]);
                *(float2*)(C + (size_t)(r0 + 8) * NOUT + col) = make_float2(af[ja][2], af[ja][3]);
            }
        } else {
            const int part = bn >> 9;            // 0=q 1=k 2=v
            const int h  = (bn & 511) >> 6;
            const int bb = r0 >> 11, nn = r0 & 2047;
            const size_t hb = ((size_t)(bb * HEADS + h) * SEQ + nn) * DHEAD;
            if (part == 0) {   // Q: split (A-operand of S)
                #pragma unroll
                for (int ja = 0; ja < 8; ++ja) {
                    const int d = ja * 8 + qq;
                    u32 hi, lo;
                    split2h(af[ja][0], af[ja][1], hi, lo);
                    *(u32*)(g_qh + hb + d) = hi;
                    *(u32*)(g_ql + hb + d) = lo;
                    split2h(af[ja][2], af[ja][3], hi, lo);
                    *(u32*)(g_qh + hb + 8 * DHEAD + d) = hi;
                    *(u32*)(g_ql + hb + 8 * DHEAD + d) = lo;
                }
            } else {           // K, V: single fp16 (B-operands)
                half* dst = (part == 1) ? g_k : g_v;
                #pragma unroll
                for (int ja = 0; ja < 8; ++ja) {
                    const int d = ja * 8 + qq;
                    *(u32*)(dst + hb + d)             = pack2h(af[ja][0], af[ja][1]);
                    *(u32*)(dst + hb + 8 * DHEAD + d) = pack2h(af[ja][2], af[ja][3]);
                }
            }
        }
    }
}

// ------------------------------------------- HMMA fp16 attention (cp.async)
// Block: 128 thr (4 warps), 64 queries of one (b,h); 32-key tiles, 2-stage ring.
// SMEM: Qh@0 (8K), Ql@8192 (8K); stage s @16384+s*8192: K (4K) + V (4K). 32K total.
// S = (Qh+Ql)@K (2 passes); PV = (Ph+Pl)@V (2 passes), P split in registers.
__global__ __launch_bounds__(128, 3)
void hmma_attn(const float* __restrict__ pose, const float* __restrict__ beta_p) {
    __shared__ __align__(128) char sm[32768];
    const u32 sb = smem_u32(sm);
    const int tid = threadIdx.x, w = tid >> 5, lane = tid & 31;
    const int q0 = blockIdx.x * 64, bh = blockIdx.y, b = bh >> 3, h = bh & 7;

    const half* kp = g_k + (size_t)bh * SEQ * DHEAD;
    const half* vp = g_v + (size_t)bh * SEQ * DHEAD;

    {
        const half* qh = g_qh + ((size_t)bh * SEQ + q0) * DHEAD;
        const half* ql = g_ql + ((size_t)bh * SEQ + q0) * DHEAD;
        #pragma unroll
        for (int i = 0; i < 4; ++i) {
            const int c = tid + i * 128, r = c >> 3, s = c & 7;
            const u32 d = r * 128 + ((s * 16) ^ ((r & 7) << 4));
            const size_t off = (size_t)r * DHEAD + s * 8;
            cpa16(sb + d,        qh + off);
            cpa16(sb + 8192 + d, ql + off);
        }
        #pragma unroll
        for (int i = 0; i < 2; ++i) {
            const int c = tid + i * 128, r = c >> 3, s = c & 7;
            const u32 d = r * 128 + ((s * 16) ^ ((r & 7) << 4));
            const size_t off = (size_t)r * DHEAD + s * 8;
            cpa16(sb + 16384 +        d, kp + off);
            cpa16(sb + 16384 + 4096 + d, vp + off);
        }
        CP_COMMIT();
    }

    const float bet = *beta_p;
    const int q  = lane >> 2;
    const int qq = (lane & 3) * 2;
    const float bq0 = bet * __ldg(&pose[(size_t)b * SEQ + q0 + w * 16 + q]);
    const float bq1 = bet * __ldg(&pose[(size_t)b * SEQ + q0 + w * 16 + q + 8]);
    const float* pb = pose + (size_t)b * SEQ;

    const u32 swz  = (u32)((lane & 7) << 4);
    const u32 aoff = (u32)((w * 16 + (lane & 15)) * 128);
    const u32 acb  = (u32)(lane & 16);
    const int brow = (lane & 7) + ((lane & 16) >> 1);
    const u32 bcb  = (u32)((lane & 8) << 1);
    const int vrow = (lane & 7) + (lane & 8);
    const u32 vcb  = (u32)(lane & 16);

    float o[8][4];
    #pragma unroll
    for (int j = 0; j < 8; ++j)
        #pragma unroll
        for (int i = 0; i < 4; ++i) o[j][i] = 0.f;
    float ls0 = 0.f, ls1 = 0.f;

    for (int t = 0; t < 64; ++t) {
        const int j0 = t * 32;
        CP_WAIT(0);
        __syncthreads();
        if (t + 1 < 64) {
            const u32 base = sb + 16384 + ((t + 1) & 1) * 8192;
            #pragma unroll
            for (int i = 0; i < 2; ++i) {
                const int c = tid + i * 128, r = c >> 3, s = c & 7;
                const u32 d = r * 128 + ((s * 16) ^ ((r & 7) << 4));
                const size_t off = (size_t)(j0 + 32 + r) * DHEAD + s * 8;
                cpa16(base +        d, kp + off);
                cpa16(base + 4096 + d, vp + off);
            }
            CP_COMMIT();
        }
        const u32 kb_ = sb + 16384 + (t & 1) * 8192;
        const u32 vb_ = kb_ + 4096;

        // ---- S = (Qh+Ql) @ K^T  (2 passes)
        float s[4][4];
        #pragma unroll
        for (int j = 0; j < 4; ++j)
            #pragma unroll
            for (int i = 0; i < 4; ++i) s[j][i] = 0.f;
        #pragma unroll
        for (int pass = 0; pass < 2; ++pass) {
            const u32 ab = sb + pass * 8192;
            #pragma unroll
            for (int ks = 0; ks < 4; ++ks) {
                const u32 kc = (u32)(ks * 32);
                u32 a0, a1, a2, a3;
                ldsm4(a0, a1, a2, a3, ab + aoff + ((kc + acb) ^ swz));
                #pragma unroll
                for (int p = 0; p < 2; ++p) {
                    u32 r0, r1, r2, r3;
                    ldsm4(r0, r1, r2, r3, kb_ + (u32)((p * 16 + brow) * 128) + ((kc + bcb) ^ swz));
                    mma16816(s[2 * p],     a0, a1, a2, a3, r0, r1);
                    mma16816(s[2 * p + 1], a0, a1, a2, a3, r2, r3);
                }
            }
        }

        // ---- softmax (unnormalized), split-P fragments in registers
        u32 Ph[2][4], Pl[2][4];
        #pragma unroll
        for (int ja = 0; ja < 4; ++ja) {
            const int col = ja * 8 + qq;
            const float bk0 = bet * __ldg(&pb[j0 + col]);
            const float bk1 = bet * __ldg(&pb[j0 + col + 1]);
            float e0 = __expf(fmaf(s[ja][0], 0.125f, bq0 + bk0));
            float e1 = __expf(fmaf(s[ja][1], 0.125f, bq0 + bk1));
            float e2 = __expf(fmaf(s[ja][2], 0.125f, bq1 + bk0));
            float e3 = __expf(fmaf(s[ja][3], 0.125f, bq1 + bk1));
            ls0 += e0 + e1;
            ls1 += e2 + e3;
            const int ka = ja >> 1, base = (ja & 1) * 2;
            split2h(e0, e1, Ph[ka][base],     Pl[ka][base]);
            split2h(e2, e3, Ph[ka][base + 1], Pl[ka][base + 1]);
        }

        // ---- O += (Ph+Pl) @ V  (2 passes)
        #pragma unroll
        for (int pass = 0; pass < 2; ++pass) {
            #pragma unroll
            for (int ks = 0; ks < 2; ++ks) {
                const u32* A = pass ? Pl[ks] : Ph[ks];
                const u32 rbase = vb_ + (u32)((ks * 16 + vrow) * 128);
                #pragma unroll
                for (int p = 0; p < 4; ++p) {
                    u32 r0, r1, r2, r3;
                    ldsm4t(r0, r1, r2, r3, rbase + ((u32)(p * 32 + vcb) ^ swz));
                    mma16816(o[2 * p],     A[0], A[1], A[2], A[3], r0, r1);
                    mma16816(o[2 * p + 1], A[0], A[1], A[2], A[3], r2, r3);
                }
            }
        }
    }

    ls0 += __shfl_xor_sync(0xffffffffu, ls0, 1);
    ls0 += __shfl_xor_sync(0xffffffffu, ls0, 2);
    ls1 += __shfl_xor_sync(0xffffffffu, ls1, 1);
    ls1 += __shfl_xor_sync(0xffffffffu, ls1, 2);
    const float inv0 = 1.0f / ls0, inv1 = 1.0f / ls1;

    const int r0 = q0 + w * 16 + q;
    #pragma unroll
    for (int ja = 0; ja < 8; ++ja) {
        const int col = h * DHEAD + ja * 8 + qq;
        u32 hi, lo;
        split2h(o[ja][0] * inv0, o[ja][1] * inv0, hi, lo);
        *(u32*)(g_aoh + ((size_t)(b * SEQ + r0)) * INNER + col) = hi;
        *(u32*)(g_aol + ((size_t)(b * SEQ + r0)) * INNER + col) = lo;
        split2h(o[ja][2] * inv1, o[ja][3] * inv1, hi, lo);
        *(u32*)(g_aoh + ((size_t)(b * SEQ + r0 + 8)) * INNER + col) = hi;
        *(u32*)(g_aol + ((size_t)(b * SEQ + r0 + 8)) * INNER + col) = lo;
    }
}

// --------------------------------------------------------------- launcher
extern "C" void kernel_launch(void* const* d_in, const int* in_sizes, int n_in,
                              void* d_out, int out_size) {
    const float* x         = (const float*)d_in[0];
    const float* pose_bias = (const float*)d_in[1];
    const float* ln_gamma  = (const float*)d_in[2];
    const float* ln_beta   = (const float*)d_in[3];
    const float* w_qkv     = (const float*)d_in[4];
    const float* w_out     = (const float*)d_in[5];
    const float* beta      = (const float*)d_in[6];
    float* out = (float*)d_out;

    ln_kernel<<<ROWS, 128>>>(x, ln_gamma, ln_beta);
    wprep_kernel<0><<<dim3(TRIPLE / 32, DIM / 32), dim3(32, 8)>>>(w_qkv);
    wprep_kernel<1><<<dim3(INNER / 32, DIM / 32), dim3(32, 8)>>>(w_out);
    hmma_gemm<TRIPLE, 0><<<dim3(TRIPLE / 64, ROWS / 128), 128>>>(nullptr);
    hmma_attn<<<dim3(SEQ / 64, BATCH * HEADS), 128>>>(pose_bias, beta);
    hmma_gemm<INNER, 1><<<dim3(INNER / 64, ROWS / 128), 128>>>(out);
}

// round 12
// speedup vs baseline: 1.7484x; 1.1918x over previous
#include <cuda_runtime.h>
#include <cuda_fp16.h>
#include <cstdint>
#include <math.h>

#define BATCH  4
#define SEQ    2048
#define DIM    512
#define HEADS  8
#define DHEAD  64
#define INNER  512
#define TRIPLE 1536
#define ROWS   (BATCH * SEQ)

typedef uint32_t u32;

// ----------------------------- device scratch ------------------------------
// X and Q split hi/lo (coherent-error paths); K, V, W, attn-out single fp16.
__device__ half g_xh [ROWS * DIM],  g_xl [ROWS * DIM];
__device__ half g_wq [TRIPLE * DIM];                        // w_qkv^T fp16 [N][K]
__device__ half g_wo [INNER * DIM];                         // w_out^T fp16
__device__ half g_qh [BATCH*HEADS*SEQ*DHEAD], g_ql[BATCH*HEADS*SEQ*DHEAD]; // [b,h,n,dh]
__device__ half g_k  [BATCH*HEADS*SEQ*DHEAD];               // [b,h,n,dh]
__device__ half g_v  [BATCH*HEADS*SEQ*DHEAD];               // [b,h,n,dh]
__device__ half g_ao [ROWS * INNER];                        // attn out fp16

// ----------------------------- helpers ---------------------------------
__device__ __forceinline__ u32 smem_u32(const void* p) {
    u32 a;
    asm("{ .reg .u64 t; cvta.to.shared.u64 t, %1; cvt.u32.u64 %0, t; }" : "=r"(a) : "l"(p));
    return a;
}
__device__ __forceinline__ void ldsm4(u32& r0, u32& r1, u32& r2, u32& r3, u32 addr) {
    asm volatile("ldmatrix.sync.aligned.m8n8.x4.shared.b16 {%0,%1,%2,%3}, [%4];"
        : "=r"(r0), "=r"(r1), "=r"(r2), "=r"(r3) : "r"(addr));
}
__device__ __forceinline__ void ldsm4t(u32& r0, u32& r1, u32& r2, u32& r3, u32 addr) {
    asm volatile("ldmatrix.sync.aligned.m8n8.x4.trans.shared.b16 {%0,%1,%2,%3}, [%4];"
        : "=r"(r0), "=r"(r1), "=r"(r2), "=r"(r3) : "r"(addr));
}
__device__ __forceinline__ void mma16816(float* c, u32 a0, u32 a1, u32 a2, u32 a3,
                                          u32 b0, u32 b1) {
    asm volatile("mma.sync.aligned.m16n8k16.row.col.f32.f16.f16.f32 "
        "{%0,%1,%2,%3}, {%4,%5,%6,%7}, {%8,%9}, {%0,%1,%2,%3};"
        : "+f"(c[0]), "+f"(c[1]), "+f"(c[2]), "+f"(c[3])
        : "r"(a0), "r"(a1), "r"(a2), "r"(a3), "r"(b0), "r"(b1));
}
__device__ __forceinline__ void cpa16(u32 dst, const void* src) {
    asm volatile("cp.async.cg.shared.global [%0], [%1], 16;" :: "r"(dst), "l"(src));
}
#define CP_COMMIT() asm volatile("cp.async.commit_group;" ::: "memory")
#define CP_WAIT(n)  asm volatile("cp.async.wait_group %0;" :: "n"(n) : "memory")

__device__ __forceinline__ void split2h(float x, float y, u32& hi, u32& lo) {
    __half2 h2 = __floats2half2_rn(x, y);
    float rx = x - __low2float(h2);
    float ry = y - __high2float(h2);
    __half2 l2 = __floats2half2_rn(rx, ry);
    hi = *reinterpret_cast<u32*>(&h2);
    lo = *reinterpret_cast<u32*>(&l2);
}
__device__ __forceinline__ u32 pack2h(float x, float y) {
    __half2 h2 = __floats2half2_rn(x, y);
    return *reinterpret_cast<u32*>(&h2);
}

// ---------------------------------------------------------------- LayerNorm
__global__ __launch_bounds__(128)
void ln_kernel(const float* __restrict__ x,
               const float* __restrict__ gamma,
               const float* __restrict__ beta) {
    const int row = blockIdx.x;
    const int t   = threadIdx.x;
    float4 v = ((const float4*)(x + (size_t)row * DIM))[t];
    float s  = v.x + v.y + v.z + v.w;
    float ss = v.x*v.x + v.y*v.y + v.z*v.z + v.w*v.w;
    #pragma unroll
    for (int o = 16; o > 0; o >>= 1) {
        s  += __shfl_xor_sync(0xffffffffu, s,  o);
        ss += __shfl_xor_sync(0xffffffffu, ss, o);
    }
    __shared__ float sh_s[4], sh_ss[4];
    const int w = t >> 5;
    if ((t & 31) == 0) { sh_s[w] = s; sh_ss[w] = ss; }
    __syncthreads();
    s  = sh_s[0] + sh_s[1] + sh_s[2] + sh_s[3];
    ss = sh_ss[0] + sh_ss[1] + sh_ss[2] + sh_ss[3];
    const float mu  = s * (1.0f / DIM);
    const float var = ss * (1.0f / DIM) - mu * mu;
    const float inv = rsqrtf(var + 1e-5f);
    float4 g  = ((const float4*)gamma)[t];
    float4 be = ((const float4*)beta)[t];
    float o0 = (v.x - mu) * inv * g.x + be.x;
    float o1 = (v.y - mu) * inv * g.y + be.y;
    float o2 = (v.z - mu) * inv * g.z + be.z;
    float o3 = (v.w - mu) * inv * g.w + be.w;
    u32 h01, l01, h23, l23;
    split2h(o0, o1, h01, l01);
    split2h(o2, o3, h23, l23);
    u32* ph = (u32*)(g_xh + (size_t)row * DIM);
    u32* pl = (u32*)(g_xl + (size_t)row * DIM);
    ph[t * 2] = h01; ph[t * 2 + 1] = h23;
    pl[t * 2] = l01; pl[t * 2 + 1] = l23;
}

// ------------------------------------------- weight transpose -> fp16
template<int WHICH>
__global__ __launch_bounds__(256)
void wprep_kernel(const float* __restrict__ w) {
    const int N = WHICH ? INNER : TRIPLE;
    half* th = WHICH ? g_wo : g_wq;
    __shared__ float t[32][33];
    const int bx = blockIdx.x * 32;   // n
    const int by = blockIdx.y * 32;   // k
    const int x = threadIdx.x, y = threadIdx.y;
    #pragma unroll
    for (int i = 0; i < 32; i += 8)
        t[y + i][x] = w[(size_t)(by + y + i) * N + bx + x];
    __syncthreads();
    #pragma unroll
    for (int i = 0; i < 32; i += 8)
        th[(size_t)(bx + y + i) * DIM + by + x] = __float2half(t[x][y + i]);
}

// ------------------------------------------- HMMA fp16 GEMM (cp.async)
// tile 128m x 64n, BK=32, 2 stages; 128 threads / 4 warps; warp = 32m x 64n.
// MODE 0 (QKV): A = (g_xh + g_xl), 2 MMA passes; scatter epilogue.
// MODE 1 (out): A = g_ao single fp16, 1 MMA pass; fp32 C.
// Stage (20480 B): Ah@0 (8K), Al@8192 (8K, MODE0 only), B@16384 (4K).
template<int NOUT, int MODE>
__global__ __launch_bounds__(128, 4)
void hmma_gemm(float* __restrict__ C) {
    __shared__ __align__(128) char sm[40960];   // 2 stages x 20480
    const u32 sb = smem_u32(sm);
    const int tid = threadIdx.x, w = tid >> 5, lane = tid & 31;
    const int bm = blockIdx.y * 128, bn = blockIdx.x * 64;

    const half* Ah = MODE ? g_ao : g_xh;
    const half* Al = MODE ? g_ao : g_xl;       // unused when MODE==1
    const half* B  = MODE ? g_wo : g_wq;

    // cp.async mapping: chunk c -> line c>>3, slot c&7; 2 rows per line
    u32 dA[4]; u32 offA[4];
    #pragma unroll
    for (int i = 0; i < 4; ++i) {
        const int c = tid + i * 128, l = c >> 3, s = c & 7;
        dA[i] = l * 128 + ((s * 16) ^ ((l & 7) << 4));
        offA[i] = (u32)((bm + l * 2 + (s >> 2)) * DIM + (s & 3) * 8);
    }
    u32 dB[2]; u32 offB[2];
    #pragma unroll
    for (int i = 0; i < 2; ++i) {
        const int c = tid + i * 128, l = c >> 3, s = c & 7;
        dB[i] = l * 128 + ((s * 16) ^ ((l & 7) << 4));
        offB[i] = (u32)((bn + l * 2 + (s >> 2)) * DIM + (s & 3) * 8);
    }

    // ldmatrix addresses (2-rows/line packing)
    const int ar0 = w * 32 + (lane & 15), ar1 = ar0 + 16;
    u32 aaddr0[2], aaddr1[2];
    #pragma unroll
    for (int ks = 0; ks < 2; ++ks) {
        const u32 kb = (u32)(lane & 16) + ks * 32;
        aaddr0[ks] = (ar0 >> 1) * 128 + ((((ar0 & 1) * 64) + kb) ^ (((ar0 >> 1) & 7) << 4));
        aaddr1[ks] = (ar1 >> 1) * 128 + ((((ar1 & 1) * 64) + kb) ^ (((ar1 >> 1) & 7) << 4));
    }
    const int brow = (lane & 7) + ((lane & 16) >> 1);
    u32 baddr[4][2];
    #pragma unroll
    for (int p = 0; p < 4; ++p) {
        const int r = p * 16 + brow;
        #pragma unroll
        for (int ks = 0; ks < 2; ++ks) {
            const u32 kb = (u32)((lane & 8) << 1) + ks * 32;
            baddr[p][ks] = (r >> 1) * 128 + ((((r & 1) * 64) + kb) ^ (((r >> 1) & 7) << 4));
        }
    }

    float acc[16][4];
    #pragma unroll
    for (int j = 0; j < 16; ++j)
        #pragma unroll
        for (int i = 0; i < 4; ++i) acc[j][i] = 0.f;

    // prologue: stage 0
    {
        #pragma unroll
        for (int i = 0; i < 4; ++i) {
            cpa16(sb + dA[i], Ah + offA[i]);
            if (MODE == 0) cpa16(sb + 8192 + dA[i], Al + offA[i]);
        }
        #pragma unroll
        for (int i = 0; i < 2; ++i)
            cpa16(sb + 16384 + dB[i], B + offB[i]);
        CP_COMMIT();
    }

    for (int kt = 0; kt < 16; ++kt) {
        CP_WAIT(0);
        __syncthreads();
        if (kt + 1 < 16) {
            const u32 base = sb + ((kt + 1) & 1) * 20480;
            const u32 ko = (u32)(kt + 1) * 32;
            #pragma unroll
            for (int i = 0; i < 4; ++i) {
                cpa16(base + dA[i], Ah + offA[i] + ko);
                if (MODE == 0) cpa16(base + 8192 + dA[i], Al + offA[i] + ko);
            }
            #pragma unroll
            for (int i = 0; i < 2; ++i)
                cpa16(base + 16384 + dB[i], B + offB[i] + ko);
            CP_COMMIT();
        }
        const u32 base = sb + (kt & 1) * 20480;
        #pragma unroll
        for (int pass = 0; pass < (MODE ? 1 : 2); ++pass) {
            const u32 ab = base + pass * 8192;
            const u32 bb = base + 16384;
            #pragma unroll
            for (int ks = 0; ks < 2; ++ks) {
                u32 a0, a1, a2, a3, a4, a5, a6, a7;
                ldsm4(a0, a1, a2, a3, ab + aaddr0[ks]);
                ldsm4(a4, a5, a6, a7, ab + aaddr1[ks]);
                #pragma unroll
                for (int p = 0; p < 4; ++p) {
                    u32 r0, r1, r2, r3;
                    ldsm4(r0, r1, r2, r3, bb + baddr[p][ks]);
                    mma16816(acc[2 * p],         a0, a1, a2, a3, r0, r1);
                    mma16816(acc[2 * p + 1],     a0, a1, a2, a3, r2, r3);
                    mma16816(acc[8 + 2 * p],     a4, a5, a6, a7, r0, r1);
                    mma16816(acc[8 + 2 * p + 1], a4, a5, a6, a7, r2, r3);
                }
            }
        }
    }

    // ---- epilogue
    const int q  = lane >> 2;
    const int qq = (lane & 3) * 2;
    #pragma unroll
    for (int half_ = 0; half_ < 2; ++half_) {
        const int r0 = bm + w * 32 + half_ * 16 + q;
        float (*af)[4] = &acc[half_ * 8];
        if (MODE == 1) {
            #pragma unroll
            for (int ja = 0; ja < 8; ++ja) {
                const int col = bn + ja * 8 + qq;
                *(float2*)(C + (size_t)r0 * NOUT + col)       = make_float2(af[ja][0], af[ja][1]);
                *(float2*)(C + (size_t)(r0 + 8) * NOUT + col) = make_float2(af[ja][2], af[ja][3]);
            }
        } else {
            const int part = bn >> 9;            // 0=q 1=k 2=v
            const int h  = (bn & 511) >> 6;
            const int bb = r0 >> 11, nn = r0 & 2047;
            const size_t hb = ((size_t)(bb * HEADS + h) * SEQ + nn) * DHEAD;
            if (part == 0) {   // Q: split (coherent logit path)
                #pragma unroll
                for (int ja = 0; ja < 8; ++ja) {
                    const int d = ja * 8 + qq;
                    u32 hi, lo;
                    split2h(af[ja][0], af[ja][1], hi, lo);
                    *(u32*)(g_qh + hb + d) = hi;
                    *(u32*)(g_ql + hb + d) = lo;
                    split2h(af[ja][2], af[ja][3], hi, lo);
                    *(u32*)(g_qh + hb + 8 * DHEAD + d) = hi;
                    *(u32*)(g_ql + hb + 8 * DHEAD + d) = lo;
                }
            } else {           // K, V: single fp16
                half* dst = (part == 1) ? g_k : g_v;
                #pragma unroll
                for (int ja = 0; ja < 8; ++ja) {
                    const int d = ja * 8 + qq;
                    *(u32*)(dst + hb + d)             = pack2h(af[ja][0], af[ja][1]);
                    *(u32*)(dst + hb + 8 * DHEAD + d) = pack2h(af[ja][2], af[ja][3]);
                }
            }
        }
    }
}

// ------------------------------------------- HMMA fp16 attention (cp.async)
// Block: 128 thr (4 warps), 64 queries of one (b,h); 32-key tiles, 2-stage ring.
// SMEM: Qh@0 (8K), Ql@8192 (8K); stage s @16384+s*8192: K (4K) + V (4K). 32K.
// S = (Qh+Ql)@K (2 passes); PV = Ph@V (1 pass, hi only — row-sum exact in fp32).
__global__ __launch_bounds__(128, 3)
void hmma_attn(const float* __restrict__ pose, const float* __restrict__ beta_p) {
    __shared__ __align__(128) char sm[32768];
    const u32 sb = smem_u32(sm);
    const int tid = threadIdx.x, w = tid >> 5, lane = tid & 31;
    const int q0 = blockIdx.x * 64, bh = blockIdx.y, b = bh >> 3, h = bh & 7;

    const half* kp = g_k + (size_t)bh * SEQ * DHEAD;
    const half* vp = g_v + (size_t)bh * SEQ * DHEAD;

    {
        const half* qh = g_qh + ((size_t)bh * SEQ + q0) * DHEAD;
        const half* ql = g_ql + ((size_t)bh * SEQ + q0) * DHEAD;
        #pragma unroll
        for (int i = 0; i < 4; ++i) {
            const int c = tid + i * 128, r = c >> 3, s = c & 7;
            const u32 d = r * 128 + ((s * 16) ^ ((r & 7) << 4));
            const size_t off = (size_t)r * DHEAD + s * 8;
            cpa16(sb + d,        qh + off);
            cpa16(sb + 8192 + d, ql + off);
        }
        #pragma unroll
        for (int i = 0; i < 2; ++i) {
            const int c = tid + i * 128, r = c >> 3, s = c & 7;
            const u32 d = r * 128 + ((s * 16) ^ ((r & 7) << 4));
            const size_t off = (size_t)r * DHEAD + s * 8;
            cpa16(sb + 16384 +        d, kp + off);
            cpa16(sb + 16384 + 4096 + d, vp + off);
        }
        CP_COMMIT();
    }

    const float bet = *beta_p;
    const int q  = lane >> 2;
    const int qq = (lane & 3) * 2;
    const float bq0 = bet * __ldg(&pose[(size_t)b * SEQ + q0 + w * 16 + q]);
    const float bq1 = bet * __ldg(&pose[(size_t)b * SEQ + q0 + w * 16 + q + 8]);
    const float* pb = pose + (size_t)b * SEQ;

    const u32 swz  = (u32)((lane & 7) << 4);
    const u32 aoff = (u32)((w * 16 + (lane & 15)) * 128);
    const u32 acb  = (u32)(lane & 16);
    const int brow = (lane & 7) + ((lane & 16) >> 1);
    const u32 bcb  = (u32)((lane & 8) << 1);
    const int vrow = (lane & 7) + (lane & 8);
    const u32 vcb  = (u32)(lane & 16);

    float o[8][4];
    #pragma unroll
    for (int j = 0; j < 8; ++j)
        #pragma unroll
        for (int i = 0; i < 4; ++i) o[j][i] = 0.f;
    float ls0 = 0.f, ls1 = 0.f;

    for (int t = 0; t < 64; ++t) {
        const int j0 = t * 32;
        CP_WAIT(0);
        __syncthreads();
        if (t + 1 < 64) {
            const u32 base = sb + 16384 + ((t + 1) & 1) * 8192;
            #pragma unroll
            for (int i = 0; i < 2; ++i) {
                const int c = tid + i * 128, r = c >> 3, s = c & 7;
                const u32 d = r * 128 + ((s * 16) ^ ((r & 7) << 4));
                const size_t off = (size_t)(j0 + 32 + r) * DHEAD + s * 8;
                cpa16(base +        d, kp + off);
                cpa16(base + 4096 + d, vp + off);
            }
            CP_COMMIT();
        }
        const u32 kb_ = sb + 16384 + (t & 1) * 8192;
        const u32 vb_ = kb_ + 4096;

        // ---- S = (Qh+Ql) @ K^T  (2 passes)
        float s[4][4];
        #pragma unroll
        for (int j = 0; j < 4; ++j)
            #pragma unroll
            for (int i = 0; i < 4; ++i) s[j][i] = 0.f;
        #pragma unroll
        for (int pass = 0; pass < 2; ++pass) {
            const u32 ab = sb + pass * 8192;
            #pragma unroll
            for (int ks = 0; ks < 4; ++ks) {
                const u32 kc = (u32)(ks * 32);
                u32 a0, a1, a2, a3;
                ldsm4(a0, a1, a2, a3, ab + aoff + ((kc + acb) ^ swz));
                #pragma unroll
                for (int p = 0; p < 2; ++p) {
                    u32 r0, r1, r2, r3;
                    ldsm4(r0, r1, r2, r3, kb_ + (u32)((p * 16 + brow) * 128) + ((kc + bcb) ^ swz));
                    mma16816(s[2 * p],     a0, a1, a2, a3, r0, r1);
                    mma16816(s[2 * p + 1], a0, a1, a2, a3, r2, r3);
                }
            }
        }

        // ---- softmax (unnormalized), hi-only P fragments (row sums exact fp32)
        u32 Ph[2][4];
        #pragma unroll
        for (int ja = 0; ja < 4; ++ja) {
            const int col = ja * 8 + qq;
            const float bk0 = bet * __ldg(&pb[j0 + col]);
            const float bk1 = bet * __ldg(&pb[j0 + col + 1]);
            float e0 = __expf(fmaf(s[ja][0], 0.125f, bq0 + bk0));
            float e1 = __expf(fmaf(s[ja][1], 0.125f, bq0 + bk1));
            float e2 = __expf(fmaf(s[ja][2], 0.125f, bq1 + bk0));
            float e3 = __expf(fmaf(s[ja][3], 0.125f, bq1 + bk1));
            ls0 += e0 + e1;
            ls1 += e2 + e3;
            const int ka = ja >> 1, base = (ja & 1) * 2;
            Ph[ka][base]     = pack2h(e0, e1);
            Ph[ka][base + 1] = pack2h(e2, e3);
        }

        // ---- O += Ph @ V  (1 pass)
        #pragma unroll
        for (int ks = 0; ks < 2; ++ks) {
            const u32* A = Ph[ks];
            const u32 rbase = vb_ + (u32)((ks * 16 + vrow) * 128);
            #pragma unroll
            for (int p = 0; p < 4; ++p) {
                u32 r0, r1, r2, r3;
                ldsm4t(r0, r1, r2, r3, rbase + ((u32)(p * 32 + vcb) ^ swz));
                mma16816(o[2 * p],     A[0], A[1], A[2], A[3], r0, r1);
                mma16816(o[2 * p + 1], A[0], A[1], A[2], A[3], r2, r3);
            }
        }
    }

    ls0 += __shfl_xor_sync(0xffffffffu, ls0, 1);
    ls0 += __shfl_xor_sync(0xffffffffu, ls0, 2);
    ls1 += __shfl_xor_sync(0xffffffffu, ls1, 1);
    ls1 += __shfl_xor_sync(0xffffffffu, ls1, 2);
    const float inv0 = 1.0f / ls0, inv1 = 1.0f / ls1;

    const int r0 = q0 + w * 16 + q;
    #pragma unroll
    for (int ja = 0; ja < 8; ++ja) {
        const int col = h * DHEAD + ja * 8 + qq;
        *(u32*)(g_ao + ((size_t)(b * SEQ + r0))     * INNER + col) =
            pack2h(o[ja][0] * inv0, o[ja][1] * inv0);
        *(u32*)(g_ao + ((size_t)(b * SEQ + r0 + 8)) * INNER + col) =
            pack2h(o[ja][2] * inv1, o[ja][3] * inv1);
    }
}

// --------------------------------------------------------------- launcher
extern "C" void kernel_launch(void* const* d_in, const int* in_sizes, int n_in,
                              void* d_out, int out_size) {
    const float* x         = (const float*)d_in[0];
    const float* pose_bias = (const float*)d_in[1];
    const float* ln_gamma  = (const float*)d_in[2];
    const float* ln_beta   = (const float*)d_in[3];
    const float* w_qkv     = (const float*)d_in[4];
    const float* w_out     = (const float*)d_in[5];
    const float* beta      = (const float*)d_in[6];
    float* out = (float*)d_out;

    ln_kernel<<<ROWS, 128>>>(x, ln_gamma, ln_beta);
    wprep_kernel<0><<<dim3(TRIPLE / 32, DIM / 32), dim3(32, 8)>>>(w_qkv);
    wprep_kernel<1><<<dim3(INNER / 32, DIM / 32), dim3(32, 8)>>>(w_out);
    hmma_gemm<TRIPLE, 0><<<dim3(TRIPLE / 64, ROWS / 128), 128>>>(nullptr);
    hmma_attn<<<dim3(SEQ / 64, BATCH * HEADS), 128>>>(pose_bias, beta);
    hmma_gemm<INNER, 1><<<dim3(INNER / 64, ROWS / 128), 128>>>(out);
}

// round 13
// speedup vs baseline: 2.6251x; 1.5015x over previous
#include <cuda_runtime.h>
#include <cuda_fp16.h>
#include <cstdint>
#include <math.h>

#define BATCH  4
#define SEQ    2048
#define DIM    512
#define HEADS  8
#define DHEAD  64
#define INNER  512
#define TRIPLE 1536
#define ROWS   (BATCH * SEQ)

typedef uint32_t u32;

// ----------------------------- device scratch ------------------------------
__device__ half g_x  [ROWS * DIM];                          // LN out fp16
__device__ half g_wq [TRIPLE * DIM];                        // w_qkv^T fp16 [N][K]
__device__ half g_wo [INNER * DIM];                         // w_out^T fp16
__device__ half g_q  [BATCH*HEADS*SEQ*DHEAD];               // [b,h,n,dh]
__device__ half g_k  [BATCH*HEADS*SEQ*DHEAD];               // [b,h,n,dh]
__device__ half g_v  [BATCH*HEADS*SEQ*DHEAD];               // [b,h,n,dh]
__device__ half g_ao [ROWS * INNER];                        // attn out fp16

// ----------------------------- helpers ---------------------------------
__device__ __forceinline__ u32 smem_u32(const void* p) {
    u32 a;
    asm("{ .reg .u64 t; cvta.to.shared.u64 t, %1; cvt.u32.u64 %0, t; }" : "=r"(a) : "l"(p));
    return a;
}
__device__ __forceinline__ void ldsm4(u32& r0, u32& r1, u32& r2, u32& r3, u32 addr) {
    asm volatile("ldmatrix.sync.aligned.m8n8.x4.shared.b16 {%0,%1,%2,%3}, [%4];"
        : "=r"(r0), "=r"(r1), "=r"(r2), "=r"(r3) : "r"(addr));
}
__device__ __forceinline__ void ldsm4t(u32& r0, u32& r1, u32& r2, u32& r3, u32 addr) {
    asm volatile("ldmatrix.sync.aligned.m8n8.x4.trans.shared.b16 {%0,%1,%2,%3}, [%4];"
        : "=r"(r0), "=r"(r1), "=r"(r2), "=r"(r3) : "r"(addr));
}
__device__ __forceinline__ void mma16816(float* c, u32 a0, u32 a1, u32 a2, u32 a3,
                                          u32 b0, u32 b1) {
    asm volatile("mma.sync.aligned.m16n8k16.row.col.f32.f16.f16.f32 "
        "{%0,%1,%2,%3}, {%4,%5,%6,%7}, {%8,%9}, {%0,%1,%2,%3};"
        : "+f"(c[0]), "+f"(c[1]), "+f"(c[2]), "+f"(c[3])
        : "r"(a0), "r"(a1), "r"(a2), "r"(a3), "r"(b0), "r"(b1));
}
__device__ __forceinline__ void cpa16(u32 dst, const void* src) {
    asm volatile("cp.async.cg.shared.global [%0], [%1], 16;" :: "r"(dst), "l"(src));
}
#define CP_COMMIT() asm volatile("cp.async.commit_group;" ::: "memory")
#define CP_WAIT(n)  asm volatile("cp.async.wait_group %0;" :: "n"(n) : "memory")

__device__ __forceinline__ u32 pack2h(float x, float y) {
    __half2 h2 = __floats2half2_rn(x, y);
    return *reinterpret_cast<u32*>(&h2);
}

// ---------------------------------------------------------------- LayerNorm
__global__ __launch_bounds__(128)
void ln_kernel(const float* __restrict__ x,
               const float* __restrict__ gamma,
               const float* __restrict__ beta) {
    const int row = blockIdx.x;
    const int t   = threadIdx.x;
    float4 v = ((const float4*)(x + (size_t)row * DIM))[t];
    float s  = v.x + v.y + v.z + v.w;
    float ss = v.x*v.x + v.y*v.y + v.z*v.z + v.w*v.w;
    #pragma unroll
    for (int o = 16; o > 0; o >>= 1) {
        s  += __shfl_xor_sync(0xffffffffu, s,  o);
        ss += __shfl_xor_sync(0xffffffffu, ss, o);
    }
    __shared__ float sh_s[4], sh_ss[4];
    const int w = t >> 5;
    if ((t & 31) == 0) { sh_s[w] = s; sh_ss[w] = ss; }
    __syncthreads();
    s  = sh_s[0] + sh_s[1] + sh_s[2] + sh_s[3];
    ss = sh_ss[0] + sh_ss[1] + sh_ss[2] + sh_ss[3];
    const float mu  = s * (1.0f / DIM);
    const float var = ss * (1.0f / DIM) - mu * mu;
    const float inv = rsqrtf(var + 1e-5f);
    float4 g  = ((const float4*)gamma)[t];
    float4 be = ((const float4*)beta)[t];
    float o0 = (v.x - mu) * inv * g.x + be.x;
    float o1 = (v.y - mu) * inv * g.y + be.y;
    float o2 = (v.z - mu) * inv * g.z + be.z;
    float o3 = (v.w - mu) * inv * g.w + be.w;
    u32* ph = (u32*)(g_x + (size_t)row * DIM);
    ph[t * 2]     = pack2h(o0, o1);
    ph[t * 2 + 1] = pack2h(o2, o3);
}

// ------------------------------------------- weight transpose -> fp16
template<int WHICH>
__global__ __launch_bounds__(256)
void wprep_kernel(const float* __restrict__ w) {
    const int N = WHICH ? INNER : TRIPLE;
    half* th = WHICH ? g_wo : g_wq;
    __shared__ float t[32][33];
    const int bx = blockIdx.x * 32;   // n
    const int by = blockIdx.y * 32;   // k
    const int x = threadIdx.x, y = threadIdx.y;
    #pragma unroll
    for (int i = 0; i < 32; i += 8)
        t[y + i][x] = w[(size_t)(by + y + i) * N + bx + x];
    __syncthreads();
    #pragma unroll
    for (int i = 0; i < 32; i += 8)
        th[(size_t)(bx + y + i) * DIM + by + x] = __float2half(t[x][y + i]);
}

// ------------------------------------------- HMMA fp16 GEMM (cp.async)
// C[8192, NOUT] = A[8192,512] @ B[512,NOUT]; tile 128m x 64n, BK=32, 3 stages.
// 128 threads / 4 warps; warp = 32m x 64n. Stage (12288 B): A@0 (8K), B@8192 (4K).
// Rows 64B; 2 rows per 128B line, SW128 XOR per line. Single fp16 pass.
// MODE 0 (QKV): A = g_x, scatter epilogue. MODE 1 (out): A = g_ao, fp32 C.
template<int NOUT, int MODE>
__global__ __launch_bounds__(128, 4)
void hmma_gemm(float* __restrict__ C) {
    __shared__ __align__(128) char sm[36864];   // 3 stages x 12288
    const u32 sb = smem_u32(sm);
    const int tid = threadIdx.x, w = tid >> 5, lane = tid & 31;
    const int bm = blockIdx.y * 128, bn = blockIdx.x * 64;

    const half* A = MODE ? g_ao : g_x;
    const half* B = MODE ? g_wo : g_wq;

    // cp.async mapping: chunk c -> line c>>3, slot c&7; 2 rows per line
    u32 dA[4]; u32 offA[4];
    #pragma unroll
    for (int i = 0; i < 4; ++i) {
        const int c = tid + i * 128, l = c >> 3, s = c & 7;
        dA[i] = l * 128 + ((s * 16) ^ ((l & 7) << 4));
        offA[i] = (u32)((bm + l * 2 + (s >> 2)) * DIM + (s & 3) * 8);
    }
    u32 dB[2]; u32 offB[2];
    #pragma unroll
    for (int i = 0; i < 2; ++i) {
        const int c = tid + i * 128, l = c >> 3, s = c & 7;
        dB[i] = l * 128 + ((s * 16) ^ ((l & 7) << 4));
        offB[i] = (u32)((bn + l * 2 + (s >> 2)) * DIM + (s & 3) * 8);
    }

    // ldmatrix addresses (2-rows/line packing)
    const int ar0 = w * 32 + (lane & 15), ar1 = ar0 + 16;
    u32 aaddr0[2], aaddr1[2];
    #pragma unroll
    for (int ks = 0; ks < 2; ++ks) {
        const u32 kb = (u32)(lane & 16) + ks * 32;
        aaddr0[ks] = (ar0 >> 1) * 128 + ((((ar0 & 1) * 64) + kb) ^ (((ar0 >> 1) & 7) << 4));
        aaddr1[ks] = (ar1 >> 1) * 128 + ((((ar1 & 1) * 64) + kb) ^ (((ar1 >> 1) & 7) << 4));
    }
    const int brow = (lane & 7) + ((lane & 16) >> 1);
    u32 baddr[4][2];
    #pragma unroll
    for (int p = 0; p < 4; ++p) {
        const int r = p * 16 + brow;
        #pragma unroll
        for (int ks = 0; ks < 2; ++ks) {
            const u32 kb = (u32)((lane & 8) << 1) + ks * 32;
            baddr[p][ks] = (r >> 1) * 128 + ((((r & 1) * 64) + kb) ^ (((r >> 1) & 7) << 4));
        }
    }

    float acc[16][4];
    #pragma unroll
    for (int j = 0; j < 16; ++j)
        #pragma unroll
        for (int i = 0; i < 4; ++i) acc[j][i] = 0.f;

    // prologue: stages 0,1
    #pragma unroll
    for (int s = 0; s < 2; ++s) {
        const u32 base = sb + s * 12288;
        const u32 ko = (u32)s * 32;
        #pragma unroll
        for (int i = 0; i < 4; ++i) cpa16(base + dA[i], A + offA[i] + ko);
        #pragma unroll
        for (int i = 0; i < 2; ++i) cpa16(base + 8192 + dB[i], B + offB[i] + ko);
        CP_COMMIT();
    }

    for (int kt = 0; kt < 16; ++kt) {
        CP_WAIT(1);
        __syncthreads();
        if (kt + 2 < 16) {
            const u32 base = sb + ((kt + 2) % 3) * 12288;
            const u32 ko = (u32)(kt + 2) * 32;
            #pragma unroll
            for (int i = 0; i < 4; ++i) cpa16(base + dA[i], A + offA[i] + ko);
            #pragma unroll
            for (int i = 0; i < 2; ++i) cpa16(base + 8192 + dB[i], B + offB[i] + ko);
            CP_COMMIT();
        }
        const u32 base = sb + (kt % 3) * 12288;
        const u32 bb = base + 8192;
        #pragma unroll
        for (int ks = 0; ks < 2; ++ks) {
            u32 a0, a1, a2, a3, a4, a5, a6, a7;
            ldsm4(a0, a1, a2, a3, base + aaddr0[ks]);
            ldsm4(a4, a5, a6, a7, base + aaddr1[ks]);
            #pragma unroll
            for (int p = 0; p < 4; ++p) {
                u32 r0, r1, r2, r3;
                ldsm4(r0, r1, r2, r3, bb + baddr[p][ks]);
                mma16816(acc[2 * p],         a0, a1, a2, a3, r0, r1);
                mma16816(acc[2 * p + 1],     a0, a1, a2, a3, r2, r3);
                mma16816(acc[8 + 2 * p],     a4, a5, a6, a7, r0, r1);
                mma16816(acc[8 + 2 * p + 1], a4, a5, a6, a7, r2, r3);
            }
        }
    }

    // ---- epilogue
    const int q  = lane >> 2;
    const int qq = (lane & 3) * 2;
    #pragma unroll
    for (int half_ = 0; half_ < 2; ++half_) {
        const int r0 = bm + w * 32 + half_ * 16 + q;
        float (*af)[4] = &acc[half_ * 8];
        if (MODE == 1) {
            #pragma unroll
            for (int ja = 0; ja < 8; ++ja) {
                const int col = bn + ja * 8 + qq;
                *(float2*)(C + (size_t)r0 * NOUT + col)       = make_float2(af[ja][0], af[ja][1]);
                *(float2*)(C + (size_t)(r0 + 8) * NOUT + col) = make_float2(af[ja][2], af[ja][3]);
            }
        } else {
            const int part = bn >> 9;            // 0=q 1=k 2=v
            half* dst = (part == 0) ? g_q : (part == 1 ? g_k : g_v);
            const int h  = (bn & 511) >> 6;
            const int bb = r0 >> 11, nn = r0 & 2047;
            const size_t hb = ((size_t)(bb * HEADS + h) * SEQ + nn) * DHEAD;
            #pragma unroll
            for (int ja = 0; ja < 8; ++ja) {
                const int d = ja * 8 + qq;
                *(u32*)(dst + hb + d)             = pack2h(af[ja][0], af[ja][1]);
                *(u32*)(dst + hb + 8 * DHEAD + d) = pack2h(af[ja][2], af[ja][3]);
            }
        }
    }
}

// ------------------------------------------- HMMA fp16 attention (cp.async)
// Block: 128 thr (4 warps), 64 queries of one (b,h); 32-key tiles, 2-stage ring.
// SMEM: Q@0 (8K); stage s @8192+s*8192: K (4K) + V (4K). 24K total.
// S = Q@K (1 pass); PV = P@V (1 pass). Row sums exact in fp32.
__global__ __launch_bounds__(128, 3)
void hmma_attn(const float* __restrict__ pose, const float* __restrict__ beta_p) {
    __shared__ __align__(128) char sm[24576];
    const u32 sb = smem_u32(sm);
    const int tid = threadIdx.x, w = tid >> 5, lane = tid & 31;
    const int q0 = blockIdx.x * 64, bh = blockIdx.y, b = bh >> 3, h = bh & 7;

    const half* kp = g_k + (size_t)bh * SEQ * DHEAD;
    const half* vp = g_v + (size_t)bh * SEQ * DHEAD;

    {
        const half* qp = g_q + ((size_t)bh * SEQ + q0) * DHEAD;
        #pragma unroll
        for (int i = 0; i < 4; ++i) {
            const int c = tid + i * 128, r = c >> 3, s = c & 7;
            const u32 d = r * 128 + ((s * 16) ^ ((r & 7) << 4));
            cpa16(sb + d, qp + (size_t)r * DHEAD + s * 8);
        }
        #pragma unroll
        for (int i = 0; i < 2; ++i) {
            const int c = tid + i * 128, r = c >> 3, s = c & 7;
            const u32 d = r * 128 + ((s * 16) ^ ((r & 7) << 4));
            const size_t off = (size_t)r * DHEAD + s * 8;
            cpa16(sb + 8192 +        d, kp + off);
            cpa16(sb + 8192 + 4096 + d, vp + off);
        }
        CP_COMMIT();
    }

    const float bet = *beta_p;
    const int q  = lane >> 2;
    const int qq = (lane & 3) * 2;
    const float bq0 = bet * __ldg(&pose[(size_t)b * SEQ + q0 + w * 16 + q]);
    const float bq1 = bet * __ldg(&pose[(size_t)b * SEQ + q0 + w * 16 + q + 8]);
    const float* pb = pose + (size_t)b * SEQ;

    const u32 swz  = (u32)((lane & 7) << 4);
    const u32 aoff = (u32)((w * 16 + (lane & 15)) * 128);
    const u32 acb  = (u32)(lane & 16);
    const int brow = (lane & 7) + ((lane & 16) >> 1);
    const u32 bcb  = (u32)((lane & 8) << 1);
    const int vrow = (lane & 7) + (lane & 8);
    const u32 vcb  = (u32)(lane & 16);

    float o[8][4];
    #pragma unroll
    for (int j = 0; j < 8; ++j)
        #pragma unroll
        for (int i = 0; i < 4; ++i) o[j][i] = 0.f;
    float ls0 = 0.f, ls1 = 0.f;

    for (int t = 0; t < 64; ++t) {
        const int j0 = t * 32;
        CP_WAIT(0);
        __syncthreads();
        if (t + 1 < 64) {
            const u32 base = sb + 8192 + ((t + 1) & 1) * 8192;
            #pragma unroll
            for (int i = 0; i < 2; ++i) {
                const int c = tid + i * 128, r = c >> 3, s = c & 7;
                const u32 d = r * 128 + ((s * 16) ^ ((r & 7) << 4));
                const size_t off = (size_t)(j0 + 32 + r) * DHEAD + s * 8;
                cpa16(base +        d, kp + off);
                cpa16(base + 4096 + d, vp + off);
            }
            CP_COMMIT();
        }
        const u32 kb_ = sb + 8192 + (t & 1) * 8192;
        const u32 vb_ = kb_ + 4096;

        // ---- S = Q @ K^T  (1 pass)
        float s[4][4];
        #pragma unroll
        for (int j = 0; j < 4; ++j)
            #pragma unroll
            for (int i = 0; i < 4; ++i) s[j][i] = 0.f;
        #pragma unroll
        for (int ks = 0; ks < 4; ++ks) {
            const u32 kc = (u32)(ks * 32);
            u32 a0, a1, a2, a3;
            ldsm4(a0, a1, a2, a3, sb + aoff + ((kc + acb) ^ swz));
            #pragma unroll
            for (int p = 0; p < 2; ++p) {
                u32 r0, r1, r2, r3;
                ldsm4(r0, r1, r2, r3, kb_ + (u32)((p * 16 + brow) * 128) + ((kc + bcb) ^ swz));
                mma16816(s[2 * p],     a0, a1, a2, a3, r0, r1);
                mma16816(s[2 * p + 1], a0, a1, a2, a3, r2, r3);
            }
        }

        // ---- softmax (unnormalized), fp16 P fragments (row sums exact fp32)
        u32 Ph[2][4];
        #pragma unroll
        for (int ja = 0; ja < 4; ++ja) {
            const int col = ja * 8 + qq;
            const float bk0 = bet * __ldg(&pb[j0 + col]);
            const float bk1 = bet * __ldg(&pb[j0 + col + 1]);
            float e0 = __expf(fmaf(s[ja][0], 0.125f, bq0 + bk0));
            float e1 = __expf(fmaf(s[ja][1], 0.125f, bq0 + bk1));
            float e2 = __expf(fmaf(s[ja][2], 0.125f, bq1 + bk0));
            float e3 = __expf(fmaf(s[ja][3], 0.125f, bq1 + bk1));
            ls0 += e0 + e1;
            ls1 += e2 + e3;
            const int ka = ja >> 1, base = (ja & 1) * 2;
            Ph[ka][base]     = pack2h(e0, e1);
            Ph[ka][base + 1] = pack2h(e2, e3);
        }

        // ---- O += P @ V  (1 pass)
        #pragma unroll
        for (int ks = 0; ks < 2; ++ks) {
            const u32* A = Ph[ks];
            const u32 rbase = vb_ + (u32)((ks * 16 + vrow) * 128);
            #pragma unroll
            for (int p = 0; p < 4; ++p) {
                u32 r0, r1, r2, r3;
                ldsm4t(r0, r1, r2, r3, rbase + ((u32)(p * 32 + vcb) ^ swz));
                mma16816(o[2 * p],     A[0], A[1], A[2], A[3], r0, r1);
                mma16816(o[2 * p + 1], A[0], A[1], A[2], A[3], r2, r3);
            }
        }
    }

    ls0 += __shfl_xor_sync(0xffffffffu, ls0, 1);
    ls0 += __shfl_xor_sync(0xffffffffu, ls0, 2);
    ls1 += __shfl_xor_sync(0xffffffffu, ls1, 1);
    ls1 += __shfl_xor_sync(0xffffffffu, ls1, 2);
    const float inv0 = 1.0f / ls0, inv1 = 1.0f / ls1;

    const int r0 = q0 + w * 16 + q;
    #pragma unroll
    for (int ja = 0; ja < 8; ++ja) {
        const int col = h * DHEAD + ja * 8 + qq;
        *(u32*)(g_ao + ((size_t)(b * SEQ + r0))     * INNER + col) =
            pack2h(o[ja][0] * inv0, o[ja][1] * inv0);
        *(u32*)(g_ao + ((size_t)(b * SEQ + r0 + 8)) * INNER + col) =
            pack2h(o[ja][2] * inv1, o[ja][3] * inv1);
    }
}

// --------------------------------------------------------------- launcher
extern "C" void kernel_launch(void* const* d_in, const int* in_sizes, int n_in,
                              void* d_out, int out_size) {
    const float* x         = (const float*)d_in[0];
    const float* pose_bias = (const float*)d_in[1];
    const float* ln_gamma  = (const float*)d_in[2];
    const float* ln_beta   = (const float*)d_in[3];
    const float* w_qkv     = (const float*)d_in[4];
    const float* w_out     = (const float*)d_in[5];
    const float* beta      = (const float*)d_in[6];
    float* out = (float*)d_out;

    ln_kernel<<<ROWS, 128>>>(x, ln_gamma, ln_beta);
    wprep_kernel<0><<<dim3(TRIPLE / 32, DIM / 32), dim3(32, 8)>>>(w_qkv);
    wprep_kernel<1><<<dim3(INNER / 32, DIM / 32), dim3(32, 8)>>>(w_out);
    hmma_gemm<TRIPLE, 0><<<dim3(TRIPLE / 64, ROWS / 128), 128>>>(nullptr);
    hmma_attn<<<dim3(SEQ / 64, BATCH * HEADS), 128>>>(pose_bias, beta);
    hmma_gemm<INNER, 1><<<dim3(INNER / 64, ROWS / 128), 128>>>(out);
}